// round 2
// baseline (speedup 1.0000x reference)
#include <cuda_runtime.h>
#include <math.h>

#define NNODES 32768
#define NBATCH 16
#define NS 2048
#define HID 64
#define HID2 128
#define ETOT 524288
#define TE 64
#define EPSF 1e-5f

// ---------------- scratch (device globals: no runtime allocation) ----------------
__device__ float g_h[NNODES * HID];
__device__ float g_agg[NNODES * HID];
__device__ float g_u[NNODES * HID];
__device__ float g_X[NNODES * 3];
__device__ float g_Y[64 * 3];
__device__ float g_acc[2 * NBATCH]; // [0..15] kXX sums, [16..31] kXY sums

// ---------------- shared-memory tile for the fused 2-layer MLP GEMMs ----------------
struct SmemT {
    float W1[HID2][HID];     // 32 KB
    float W2[HID][HID];      // 16 KB
    float b1[HID];
    float b2[HID];
    float In[HID2][TE + 4];  // transposed input tile [k][e], padded (68 floats/row, 16B-aligned rows)
    float Mid[HID][TE + 4];  // transposed mid tile
    int   dst[TE];
};

// fast exp for x in [-8, 0.5]; FFMA-only (avoids MUFU throughput wall), rel err ~3e-6
__device__ __forceinline__ float fexp(float x) {
    const float L2E = 1.4426950408889634f;
    float t = fmaf(x, L2E, 12582912.0f);     // round-to-nearest via magic number
    float kf = t - 12582912.0f;
    float f = fmaf(x, L2E, -kf);             // f in [-0.5, 0.5]
    float p = 1.33335581e-3f;                // Taylor of 2^f
    p = fmaf(p, f, 9.61812911e-3f);
    p = fmaf(p, f, 5.55041087e-2f);
    p = fmaf(p, f, 2.40226507e-1f);
    p = fmaf(p, f, 6.93147181e-1f);
    p = fmaf(p, f, 1.0f);
    int ik = (int)kf;
    return __int_as_float(__float_as_int(p) + (ik << 23));
}

// ---------------- Y = fibonacci_sphere(64), computed in double to match numpy ----------------
__global__ void compute_Y_kernel() {
    int i = threadIdx.x;
    if (i < 64) {
        double phi = 3.14159265358979323846 * (3.0 - sqrt(5.0));
        double y = 1.0 - 2.0 * (double)i / 63.0;
        double r = sqrt(fmax(0.0, 1.0 - y * y));
        double th = phi * (double)i;
        g_Y[i * 3 + 0] = (float)(cos(th) * r);
        g_Y[i * 3 + 1] = (float)y;
        g_Y[i * 3 + 2] = (float)(sin(th) * r);
    }
}

__global__ void zero_agg_kernel() {
    int i = blockIdx.x * blockDim.x + threadIdx.x; // NNODES*HID/4 float4s
    reinterpret_cast<float4*>(g_agg)[i] = make_float4(0.f, 0.f, 0.f, 0.f);
}

__global__ void zero_acc_kernel() {
    int i = threadIdx.x;
    if (i < 2 * NBATCH) g_acc[i] = 0.f;
}

// ---------------- encoder: h = x @ enc_W + enc_b ----------------
__global__ void encoder_kernel(const float* __restrict__ x,
                               const float* __restrict__ W,
                               const float* __restrict__ b) {
    __shared__ float sW[3 * HID];
    __shared__ float sb[HID];
    int t = threadIdx.x;
    if (t < 3 * HID) sW[t] = W[t];
    if (t < HID) sb[t] = b[t];
    __syncthreads();
    int idx = blockIdx.x * 256 + t;       // over NNODES*HID
    int n = idx >> 6, c = idx & 63;
    float x0 = x[n * 3 + 0], x1 = x[n * 3 + 1], x2 = x[n * 3 + 2];
    g_h[idx] = fmaf(x0, sW[c], fmaf(x1, sW[HID + c], fmaf(x2, sW[2 * HID + c], sb[c])));
}

// ---------------- edge MLP: m = relu(relu([h[dst],h[src]]@W1+b1)@W2+b2); agg[dst] += m ----------------
__global__ void __launch_bounds__(256, 2) edge_mlp_kernel(
    const float* __restrict__ W1g, const float* __restrict__ b1g,
    const float* __restrict__ W2g, const float* __restrict__ b2g,
    const int* __restrict__ esrc, const int* __restrict__ edst) {
    extern __shared__ char sraw[];
    SmemT& s = *reinterpret_cast<SmemT*>(sraw);
    const int t = threadIdx.x;
    for (int i = t; i < HID2 * HID; i += 256) s.W1[i >> 6][i & 63] = W1g[i];
    for (int i = t; i < HID * HID; i += 256) s.W2[i >> 6][i & 63] = W2g[i];
    if (t < HID) { s.b1[t] = b1g[t]; s.b2[t] = b2g[t]; }
    const int e0 = (t & 15) * 4, c0 = (t >> 4) * 4;
    const int ntiles = ETOT / TE;
    for (int tile = blockIdx.x; tile < ntiles; tile += gridDim.x) {
        const int base = tile * TE;
        __syncthreads(); // previous iteration fully done with s.Mid / s.dst / s.In
        if (t < TE) s.dst[t] = edst[base + t];
        #pragma unroll
        for (int i = t; i < TE * 32; i += 256) {
            int e = i >> 5, rest = i & 31, half = rest >> 4, q = rest & 15;
            int node = half ? esrc[base + e] : edst[base + e];
            float4 v = reinterpret_cast<const float4*>(g_h)[node * 16 + q];
            int k = (half << 6) + (q << 2);
            s.In[k + 0][e] = v.x; s.In[k + 1][e] = v.y;
            s.In[k + 2][e] = v.z; s.In[k + 3][e] = v.w;
        }
        __syncthreads();
        // GEMM1: [64e x 128k] @ [128k x 64c], per-thread 4x4
        float acc[4][4];
        #pragma unroll
        for (int i = 0; i < 4; i++)
            #pragma unroll
            for (int j = 0; j < 4; j++) acc[i][j] = s.b1[c0 + j];
        #pragma unroll 4
        for (int k = 0; k < HID2; k++) {
            float4 av = *reinterpret_cast<const float4*>(&s.In[k][e0]);
            float4 wv = *reinterpret_cast<const float4*>(&s.W1[k][c0]);
            float aa[4] = {av.x, av.y, av.z, av.w};
            float ww[4] = {wv.x, wv.y, wv.z, wv.w};
            #pragma unroll
            for (int i = 0; i < 4; i++)
                #pragma unroll
                for (int j = 0; j < 4; j++) acc[i][j] = fmaf(aa[i], ww[j], acc[i][j]);
        }
        #pragma unroll
        for (int i = 0; i < 4; i++)
            #pragma unroll
            for (int j = 0; j < 4; j++) s.Mid[c0 + j][e0 + i] = fmaxf(acc[i][j], 0.f);
        __syncthreads();
        // GEMM2: [64e x 64k] @ [64k x 64c]
        float acc2[4][4];
        #pragma unroll
        for (int i = 0; i < 4; i++)
            #pragma unroll
            for (int j = 0; j < 4; j++) acc2[i][j] = s.b2[c0 + j];
        #pragma unroll 4
        for (int k = 0; k < HID; k++) {
            float4 av = *reinterpret_cast<const float4*>(&s.Mid[k][e0]);
            float4 wv = *reinterpret_cast<const float4*>(&s.W2[k][c0]);
            float aa[4] = {av.x, av.y, av.z, av.w};
            float ww[4] = {wv.x, wv.y, wv.z, wv.w};
            #pragma unroll
            for (int i = 0; i < 4; i++)
                #pragma unroll
                for (int j = 0; j < 4; j++) acc2[i][j] = fmaf(aa[i], ww[j], acc2[i][j]);
        }
        #pragma unroll
        for (int i = 0; i < 4; i++) {
            float* p = &g_agg[(size_t)s.dst[e0 + i] * HID + c0];
            float v0 = fmaxf(acc2[i][0], 0.f), v1 = fmaxf(acc2[i][1], 0.f);
            float v2 = fmaxf(acc2[i][2], 0.f), v3 = fmaxf(acc2[i][3], 0.f);
            asm volatile("red.global.add.v4.f32 [%0], {%1,%2,%3,%4};"
                         :: "l"(p), "f"(v0), "f"(v1), "f"(v2), "f"(v3) : "memory");
        }
    }
}

// ---------------- node MLP: u = relu(relu([h,agg]@U1+b1)@U2+b2) -> g_u ----------------
__global__ void __launch_bounds__(256, 2) node_mlp_kernel(
    const float* __restrict__ W1g, const float* __restrict__ b1g,
    const float* __restrict__ W2g, const float* __restrict__ b2g) {
    extern __shared__ char sraw[];
    SmemT& s = *reinterpret_cast<SmemT*>(sraw);
    const int t = threadIdx.x;
    for (int i = t; i < HID2 * HID; i += 256) s.W1[i >> 6][i & 63] = W1g[i];
    for (int i = t; i < HID * HID; i += 256) s.W2[i >> 6][i & 63] = W2g[i];
    if (t < HID) { s.b1[t] = b1g[t]; s.b2[t] = b2g[t]; }
    const int e0 = (t & 15) * 4, c0 = (t >> 4) * 4;
    const int ntiles = NNODES / TE;
    for (int tile = blockIdx.x; tile < ntiles; tile += gridDim.x) {
        const int base = tile * TE;
        __syncthreads();
        #pragma unroll
        for (int i = t; i < TE * 32; i += 256) {
            int e = i >> 5, rest = i & 31, half = rest >> 4, q = rest & 15;
            const float* src = half ? g_agg : g_h;
            float4 v = reinterpret_cast<const float4*>(src)[(base + e) * 16 + q];
            int k = (half << 6) + (q << 2);
            s.In[k + 0][e] = v.x; s.In[k + 1][e] = v.y;
            s.In[k + 2][e] = v.z; s.In[k + 3][e] = v.w;
        }
        __syncthreads();
        float acc[4][4];
        #pragma unroll
        for (int i = 0; i < 4; i++)
            #pragma unroll
            for (int j = 0; j < 4; j++) acc[i][j] = s.b1[c0 + j];
        #pragma unroll 4
        for (int k = 0; k < HID2; k++) {
            float4 av = *reinterpret_cast<const float4*>(&s.In[k][e0]);
            float4 wv = *reinterpret_cast<const float4*>(&s.W1[k][c0]);
            float aa[4] = {av.x, av.y, av.z, av.w};
            float ww[4] = {wv.x, wv.y, wv.z, wv.w};
            #pragma unroll
            for (int i = 0; i < 4; i++)
                #pragma unroll
                for (int j = 0; j < 4; j++) acc[i][j] = fmaf(aa[i], ww[j], acc[i][j]);
        }
        #pragma unroll
        for (int i = 0; i < 4; i++)
            #pragma unroll
            for (int j = 0; j < 4; j++) s.Mid[c0 + j][e0 + i] = fmaxf(acc[i][j], 0.f);
        __syncthreads();
        float acc2[4][4];
        #pragma unroll
        for (int i = 0; i < 4; i++)
            #pragma unroll
            for (int j = 0; j < 4; j++) acc2[i][j] = s.b2[c0 + j];
        #pragma unroll 4
        for (int k = 0; k < HID; k++) {
            float4 av = *reinterpret_cast<const float4*>(&s.Mid[k][e0]);
            float4 wv = *reinterpret_cast<const float4*>(&s.W2[k][c0]);
            float aa[4] = {av.x, av.y, av.z, av.w};
            float ww[4] = {wv.x, wv.y, wv.z, wv.w};
            #pragma unroll
            for (int i = 0; i < 4; i++)
                #pragma unroll
                for (int j = 0; j < 4; j++) acc2[i][j] = fmaf(aa[i], ww[j], acc2[i][j]);
        }
        #pragma unroll
        for (int i = 0; i < 4; i++) {
            float4 v = make_float4(fmaxf(acc2[i][0], 0.f), fmaxf(acc2[i][1], 0.f),
                                   fmaxf(acc2[i][2], 0.f), fmaxf(acc2[i][3], 0.f));
            *reinterpret_cast<float4*>(&g_u[(size_t)(base + e0 + i) * HID + c0]) = v;
        }
    }
}

// ---------------- InstanceNorm per (graph, channel), two-pass, writes g_h ----------------
__global__ void instnorm_kernel() {
    int g = blockIdx.x;
    int t = threadIdx.x;       // 512 threads
    int c = t & 63, r = t >> 6; // r in 0..7
    const float* base = g_u + (size_t)g * NS * HID;
    float* out = g_h + (size_t)g * NS * HID;
    __shared__ float red[8][64];
    float s = 0.f;
    for (int n = r; n < NS; n += 8) s += base[n * HID + c];
    red[r][c] = s;
    __syncthreads();
    if (r == 0) {
        float tot = 0.f;
        #pragma unroll
        for (int i = 0; i < 8; i++) tot += red[i][c];
        red[0][c] = tot * (1.0f / NS);
    }
    __syncthreads();
    float mean = red[0][c];
    __syncthreads();
    float s2 = 0.f;
    for (int n = r; n < NS; n += 8) { float d = base[n * HID + c] - mean; s2 = fmaf(d, d, s2); }
    red[r][c] = s2;
    __syncthreads();
    if (r == 0) {
        float tot = 0.f;
        #pragma unroll
        for (int i = 0; i < 8; i++) tot += red[i][c];
        red[0][c] = rsqrtf(tot * (1.0f / NS) + EPSF);
    }
    __syncthreads();
    float inv = red[0][c];
    for (int n = r; n < NS; n += 8) out[n * HID + c] = (base[n * HID + c] - mean) * inv;
}

// ---------------- decoder: X = normalize(h @ dec_W + dec_b); writes g_X and d_out[1..] ----------------
__global__ void decoder_kernel(const float* __restrict__ W, const float* __restrict__ b,
                               float* __restrict__ out) {
    __shared__ float sW[HID * 3];
    __shared__ float sb[3];
    int t = threadIdx.x;
    if (t < HID * 3) sW[t] = W[t];
    if (t < 3) sb[t] = b[t];
    __syncthreads();
    int n = blockIdx.x * 256 + t;
    float a0 = sb[0], a1 = sb[1], a2 = sb[2];
    const float* hr = g_h + (size_t)n * HID;
    #pragma unroll 8
    for (int k = 0; k < HID; k++) {
        float v = hr[k];
        a0 = fmaf(v, sW[k * 3 + 0], a0);
        a1 = fmaf(v, sW[k * 3 + 1], a1);
        a2 = fmaf(v, sW[k * 3 + 2], a2);
    }
    float inv = rsqrtf(a0 * a0 + a1 * a1 + a2 * a2);
    a0 *= inv; a1 *= inv; a2 *= inv;
    g_X[n * 3 + 0] = a0; g_X[n * 3 + 1] = a1; g_X[n * 3 + 2] = a2;
    out[1 + n * 3 + 0] = a0; out[1 + n * 3 + 1] = a1; out[1 + n * 3 + 2] = a2;
}

// ---------------- MMD: kXX per-graph sums ----------------
__global__ void kxx_kernel() {
    int bid = blockIdx.x;                 // NBATCH*16*16
    int g = bid >> 8, tm = (bid >> 4) & 15, tn = bid & 15;
    const float* Xg = g_X + (size_t)g * NS * 3;
    __shared__ float ax[128][4];
    __shared__ float ay[128][4];
    __shared__ float rs[256];
    int t = threadIdx.x;
    for (int i = t; i < 128 * 3; i += 256) {
        int row = i / 3, col = i - row * 3;
        ax[row][col] = Xg[tm * 128 * 3 + i];
        ay[row][col] = Xg[tn * 128 * 3 + i];
    }
    __syncthreads();
    int r0 = (t >> 4) << 3, cb = (t & 15) << 3;
    float yv[8][3];
    #pragma unroll
    for (int j = 0; j < 8; j++) {
        yv[j][0] = ay[cb + j][0]; yv[j][1] = ay[cb + j][1]; yv[j][2] = ay[cb + j][2];
    }
    float s = 0.f;
    #pragma unroll
    for (int i = 0; i < 8; i++) {
        float x0 = ax[r0 + i][0], x1 = ax[r0 + i][1], x2 = ax[r0 + i][2];
        #pragma unroll
        for (int j = 0; j < 8; j++) {
            float d = fmaf(x0, yv[j][0], fmaf(x1, yv[j][1], x2 * yv[j][2]));
            s += fexp(fmaf(2.f, d, -2.f));
        }
    }
    rs[t] = s;
    __syncthreads();
    for (int o = 128; o > 0; o >>= 1) { if (t < o) rs[t] += rs[t + o]; __syncthreads(); }
    if (t == 0) atomicAdd(&g_acc[g], rs[0]);
}

// ---------------- MMD: kXY per-graph sums ----------------
__global__ void kxy_kernel() {
    __shared__ float sy[64][4];
    __shared__ float rs[256];
    int t = threadIdx.x;
    int n = blockIdx.x * 256 + t;
    for (int i = t; i < 64 * 3; i += 256) { int row = i / 3; sy[row][i - row * 3] = g_Y[i]; }
    __syncthreads();
    float x0 = g_X[n * 3], x1 = g_X[n * 3 + 1], x2 = g_X[n * 3 + 2];
    float s = 0.f;
    #pragma unroll 8
    for (int j = 0; j < 64; j++) {
        float d = fmaf(x0, sy[j][0], fmaf(x1, sy[j][1], x2 * sy[j][2]));
        s += fexp(fmaf(2.f, d, -2.f));
    }
    rs[t] = s;
    __syncthreads();
    for (int o = 128; o > 0; o >>= 1) { if (t < o) rs[t] += rs[t + o]; __syncthreads(); }
    if (t == 0) atomicAdd(&g_acc[NBATCH + (n >> 11)], rs[0]);
}

// ---------------- finalize: kYY + loss -> out[0] ----------------
__global__ void finalize_kernel(float* __restrict__ out) {
    __shared__ float rs[64];
    int t = threadIdx.x; // 64
    float x0 = g_Y[t * 3], x1 = g_Y[t * 3 + 1], x2 = g_Y[t * 3 + 2];
    float s = 0.f;
    for (int j = 0; j < 64; j++) {
        float d = fmaf(x0, g_Y[j * 3], fmaf(x1, g_Y[j * 3 + 1], x2 * g_Y[j * 3 + 2]));
        s += fexp(fmaf(2.f, d, -2.f));
    }
    rs[t] = s;
    __syncthreads();
    if (t == 0) {
        float kyy = 0.f;
        for (int j = 0; j < 64; j++) kyy += rs[j];
        kyy *= (1.0f / (64.f * 64.f));
        float loss = 0.f;
        for (int b = 0; b < NBATCH; b++) {
            float kxx = g_acc[b] * (1.0f / ((float)NS * (float)NS));
            float kxy = g_acc[NBATCH + b] * (1.0f / ((float)NS * 64.f));
            loss += kxx - 2.f * kxy + kyy;
        }
        out[0] = loss * (1.0f / NBATCH);
    }
}

// ---------------- launch ----------------
extern "C" void kernel_launch(void* const* d_in, const int* in_sizes, int n_in,
                              void* d_out, int out_size) {
    const float* x    = (const float*)d_in[0];
    const int*   esrc = (const int*)d_in[1];
    const int*   edst = (const int*)d_in[2];
    // d_in[3] = nbatch (compile-time constant NBATCH)
    const float* encW = (const float*)d_in[4];
    const float* encb = (const float*)d_in[5];
    const float* m1W  = (const float*)d_in[6];
    const float* m1b  = (const float*)d_in[7];
    const float* m2W  = (const float*)d_in[8];
    const float* m2b  = (const float*)d_in[9];
    const float* u1W  = (const float*)d_in[10];
    const float* u1b  = (const float*)d_in[11];
    const float* u2W  = (const float*)d_in[12];
    const float* u2b  = (const float*)d_in[13];
    const float* decW = (const float*)d_in[14];
    const float* decb = (const float*)d_in[15];
    float* out = (float*)d_out;

    cudaFuncSetAttribute((const void*)edge_mlp_kernel,
                         cudaFuncAttributeMaxDynamicSharedMemorySize, (int)sizeof(SmemT));
    cudaFuncSetAttribute((const void*)node_mlp_kernel,
                         cudaFuncAttributeMaxDynamicSharedMemorySize, (int)sizeof(SmemT));

    compute_Y_kernel<<<1, 64>>>();
    encoder_kernel<<<NNODES * HID / 256, 256>>>(x, encW, encb);

    for (int l = 0; l < 4; l++) {
        zero_agg_kernel<<<NNODES * HID / 1024, 256>>>();
        edge_mlp_kernel<<<296, 256, sizeof(SmemT)>>>(
            m1W + (size_t)l * HID2 * HID, m1b + (size_t)l * HID,
            m2W + (size_t)l * HID * HID,  m2b + (size_t)l * HID, esrc, edst);
        node_mlp_kernel<<<296, 256, sizeof(SmemT)>>>(
            u1W + (size_t)l * HID2 * HID, u1b + (size_t)l * HID,
            u2W + (size_t)l * HID * HID,  u2b + (size_t)l * HID);
        instnorm_kernel<<<NBATCH, 512>>>();
    }

    zero_acc_kernel<<<1, 32>>>();
    decoder_kernel<<<NNODES / 256, 256>>>(decW, decb, out);
    kxy_kernel<<<NNODES / 256, 256>>>();
    kxx_kernel<<<NBATCH * 16 * 16, 256>>>();
    finalize_kernel<<<1, 64>>>(out);
}

// round 3
// speedup vs baseline: 1.2377x; 1.2377x over previous
#include <cuda_runtime.h>
#include <math.h>

#define NNODES 32768
#define NBATCH 16
#define NS 2048
#define HID 64
#define HID2 128
#define ETOT 524288
#define TE 256
#define EPSF 1e-5f

// ---------------- scratch ----------------
__device__ float g_h[NNODES * HID];
__device__ float g_agg[NNODES * HID];
__device__ float g_u[NNODES * HID];
__device__ float g_X[NNODES * 3];
__device__ float g_Y[64 * 3];
__device__ float g_acc[2 * NBATCH];

// ---------------- smem for fused 2-layer MLP ----------------
struct SmemG {
    float W1[HID2][HID];   // 32 KB
    float W2[HID][HID];    // 16 KB
    float b1[HID];
    float b2[HID];
    float In[HID][TE];     // K-half staging, [k][e], 64 KB
    float Mid[HID][TE];    // 64 KB
    int   dst[TE];
    int   src[TE];
};

// fast exp, FFMA-only
__device__ __forceinline__ float fexp(float x) {
    const float L2E = 1.4426950408889634f;
    float t = fmaf(x, L2E, 12582912.0f);
    float kf = t - 12582912.0f;
    float f = fmaf(x, L2E, -kf);
    float p = 1.33335581e-3f;
    p = fmaf(p, f, 9.61812911e-3f);
    p = fmaf(p, f, 5.55041087e-2f);
    p = fmaf(p, f, 2.40226507e-1f);
    p = fmaf(p, f, 6.93147181e-1f);
    p = fmaf(p, f, 1.0f);
    int ik = (int)kf;
    return __int_as_float(__float_as_int(p) + (ik << 23));
}

__global__ void compute_Y_kernel() {
    int i = threadIdx.x;
    if (i < 64) {
        double phi = 3.14159265358979323846 * (3.0 - sqrt(5.0));
        double y = 1.0 - 2.0 * (double)i / 63.0;
        double r = sqrt(fmax(0.0, 1.0 - y * y));
        double th = phi * (double)i;
        g_Y[i * 3 + 0] = (float)(cos(th) * r);
        g_Y[i * 3 + 1] = (float)y;
        g_Y[i * 3 + 2] = (float)(sin(th) * r);
    }
}

__global__ void zero_agg_kernel() {
    int i = blockIdx.x * blockDim.x + threadIdx.x;
    reinterpret_cast<float4*>(g_agg)[i] = make_float4(0.f, 0.f, 0.f, 0.f);
}

__global__ void zero_acc_kernel() {
    int i = threadIdx.x;
    if (i < 2 * NBATCH) g_acc[i] = 0.f;
}

__global__ void encoder_kernel(const float* __restrict__ x,
                               const float* __restrict__ W,
                               const float* __restrict__ b) {
    __shared__ float sW[3 * HID];
    __shared__ float sb[HID];
    int t = threadIdx.x;
    if (t < 3 * HID) sW[t] = W[t];
    if (t < HID) sb[t] = b[t];
    __syncthreads();
    int idx = blockIdx.x * 256 + t;
    int n = idx >> 6, c = idx & 63;
    float x0 = x[n * 3 + 0], x1 = x[n * 3 + 1], x2 = x[n * 3 + 2];
    g_h[idx] = fmaf(x0, sW[c], fmaf(x1, sW[HID + c], fmaf(x2, sW[2 * HID + c], sb[c])));
}

// ======== shared GEMM helpers (thread = 2 edges x 32 cols, W broadcast) ========
// acc layout: acc[0..31] = edge eA, acc[32..63] = edge eA+32, cols cg..cg+31

__device__ __forceinline__ void gemm_half(const float (*In)[TE], const float (*W)[HID],
                                          int koff, int eA, int cg, float* acc) {
    #pragma unroll 2
    for (int kk = 0; kk < 64; kk++) {
        float a0 = In[kk][eA];
        float a1 = In[kk][eA + 32];
        const float4* w4 = reinterpret_cast<const float4*>(&W[koff + kk][cg]);
        #pragma unroll
        for (int j = 0; j < 8; j++) {
            float4 w = w4[j];
            acc[4 * j + 0] = fmaf(a0, w.x, acc[4 * j + 0]);
            acc[4 * j + 1] = fmaf(a0, w.y, acc[4 * j + 1]);
            acc[4 * j + 2] = fmaf(a0, w.z, acc[4 * j + 2]);
            acc[4 * j + 3] = fmaf(a0, w.w, acc[4 * j + 3]);
            acc[32 + 4 * j + 0] = fmaf(a1, w.x, acc[32 + 4 * j + 0]);
            acc[32 + 4 * j + 1] = fmaf(a1, w.y, acc[32 + 4 * j + 1]);
            acc[32 + 4 * j + 2] = fmaf(a1, w.z, acc[32 + 4 * j + 2]);
            acc[32 + 4 * j + 3] = fmaf(a1, w.w, acc[32 + 4 * j + 3]);
        }
    }
}

// ---------------- edge MLP ----------------
__global__ void __launch_bounds__(256, 1) edge_mlp_kernel(
    const float* __restrict__ W1g, const float* __restrict__ b1g,
    const float* __restrict__ W2g, const float* __restrict__ b2g,
    const int* __restrict__ esrc, const int* __restrict__ edst) {
    extern __shared__ char sraw[];
    SmemG& s = *reinterpret_cast<SmemG*>(sraw);
    const int t = threadIdx.x;
    for (int i = t; i < HID2 * HID; i += 256) (&s.W1[0][0])[i] = W1g[i];
    for (int i = t; i < HID * HID; i += 256) (&s.W2[0][0])[i] = W2g[i];
    if (t < HID) { s.b1[t] = b1g[t]; s.b2[t] = b2g[t]; }
    const int lane = t & 31, wid = t >> 5;
    const int eA = (wid & 3) * 64 + lane;   // edges eA, eA+32
    const int cg = (wid >> 2) * 32;         // 32-col slab
    const int ntiles = ETOT / TE;
    for (int tile = blockIdx.x; tile < ntiles; tile += gridDim.x) {
        const int base = tile * TE;
        __syncthreads();                                   // S1: prev tile fully done
        s.dst[t] = edst[base + t];
        s.src[t] = esrc[base + t];
        __syncthreads();                                   // S2
        // gather half 0: h[dst]
        {
            const float4* hp = reinterpret_cast<const float4*>(g_h) + (size_t)s.dst[t] * 16;
            #pragma unroll
            for (int q = 0; q < 16; q++) {
                float4 v = hp[q];
                s.In[q * 4 + 0][t] = v.x; s.In[q * 4 + 1][t] = v.y;
                s.In[q * 4 + 2][t] = v.z; s.In[q * 4 + 3][t] = v.w;
            }
        }
        __syncthreads();                                   // S3
        float acc[64];
        {
            float b;
            #pragma unroll
            for (int j = 0; j < 32; j++) { b = s.b1[cg + j]; acc[j] = b; acc[32 + j] = b; }
        }
        gemm_half(s.In, s.W1, 0, eA, cg, acc);
        __syncthreads();                                   // S4: done reading In half0
        // gather half 1: h[src]
        {
            const float4* hp = reinterpret_cast<const float4*>(g_h) + (size_t)s.src[t] * 16;
            #pragma unroll
            for (int q = 0; q < 16; q++) {
                float4 v = hp[q];
                s.In[q * 4 + 0][t] = v.x; s.In[q * 4 + 1][t] = v.y;
                s.In[q * 4 + 2][t] = v.z; s.In[q * 4 + 3][t] = v.w;
            }
        }
        __syncthreads();                                   // S5
        gemm_half(s.In, s.W1, 64, eA, cg, acc);
        #pragma unroll
        for (int j = 0; j < 32; j++) {
            s.Mid[cg + j][eA]      = fmaxf(acc[j], 0.f);
            s.Mid[cg + j][eA + 32] = fmaxf(acc[32 + j], 0.f);
        }
        __syncthreads();                                   // S6
        float acc2[64];
        {
            float b;
            #pragma unroll
            for (int j = 0; j < 32; j++) { b = s.b2[cg + j]; acc2[j] = b; acc2[32 + j] = b; }
        }
        gemm_half(s.Mid, s.W2, 0, eA, cg, acc2);
        // scatter-add (relu applied)
        {
            float* p0 = &g_agg[(size_t)s.dst[eA] * HID + cg];
            #pragma unroll
            for (int j = 0; j < 8; j++) {
                float v0 = fmaxf(acc2[4 * j + 0], 0.f), v1 = fmaxf(acc2[4 * j + 1], 0.f);
                float v2 = fmaxf(acc2[4 * j + 2], 0.f), v3 = fmaxf(acc2[4 * j + 3], 0.f);
                asm volatile("red.global.add.v4.f32 [%0], {%1,%2,%3,%4};"
                             :: "l"(p0 + 4 * j), "f"(v0), "f"(v1), "f"(v2), "f"(v3) : "memory");
            }
            float* p1 = &g_agg[(size_t)s.dst[eA + 32] * HID + cg];
            #pragma unroll
            for (int j = 0; j < 8; j++) {
                float v0 = fmaxf(acc2[32 + 4 * j + 0], 0.f), v1 = fmaxf(acc2[32 + 4 * j + 1], 0.f);
                float v2 = fmaxf(acc2[32 + 4 * j + 2], 0.f), v3 = fmaxf(acc2[32 + 4 * j + 3], 0.f);
                asm volatile("red.global.add.v4.f32 [%0], {%1,%2,%3,%4};"
                             :: "l"(p1 + 4 * j), "f"(v0), "f"(v1), "f"(v2), "f"(v3) : "memory");
            }
        }
    }
}

// ---------------- node MLP ----------------
__global__ void __launch_bounds__(256, 1) node_mlp_kernel(
    const float* __restrict__ W1g, const float* __restrict__ b1g,
    const float* __restrict__ W2g, const float* __restrict__ b2g) {
    extern __shared__ char sraw[];
    SmemG& s = *reinterpret_cast<SmemG*>(sraw);
    const int t = threadIdx.x;
    for (int i = t; i < HID2 * HID; i += 256) (&s.W1[0][0])[i] = W1g[i];
    for (int i = t; i < HID * HID; i += 256) (&s.W2[0][0])[i] = W2g[i];
    if (t < HID) { s.b1[t] = b1g[t]; s.b2[t] = b2g[t]; }
    const int lane = t & 31, wid = t >> 5;
    const int eA = (wid & 3) * 64 + lane;
    const int cg = (wid >> 2) * 32;
    const int ntiles = NNODES / TE;
    for (int tile = blockIdx.x; tile < ntiles; tile += gridDim.x) {
        const int base = tile * TE;
        __syncthreads();
        // half 0: h
        {
            const float4* hp = reinterpret_cast<const float4*>(g_h) + (size_t)(base + t) * 16;
            #pragma unroll
            for (int q = 0; q < 16; q++) {
                float4 v = hp[q];
                s.In[q * 4 + 0][t] = v.x; s.In[q * 4 + 1][t] = v.y;
                s.In[q * 4 + 2][t] = v.z; s.In[q * 4 + 3][t] = v.w;
            }
        }
        __syncthreads();
        float acc[64];
        {
            float b;
            #pragma unroll
            for (int j = 0; j < 32; j++) { b = s.b1[cg + j]; acc[j] = b; acc[32 + j] = b; }
        }
        gemm_half(s.In, s.W1, 0, eA, cg, acc);
        __syncthreads();
        // half 1: agg
        {
            const float4* hp = reinterpret_cast<const float4*>(g_agg) + (size_t)(base + t) * 16;
            #pragma unroll
            for (int q = 0; q < 16; q++) {
                float4 v = hp[q];
                s.In[q * 4 + 0][t] = v.x; s.In[q * 4 + 1][t] = v.y;
                s.In[q * 4 + 2][t] = v.z; s.In[q * 4 + 3][t] = v.w;
            }
        }
        __syncthreads();
        gemm_half(s.In, s.W1, 64, eA, cg, acc);
        #pragma unroll
        for (int j = 0; j < 32; j++) {
            s.Mid[cg + j][eA]      = fmaxf(acc[j], 0.f);
            s.Mid[cg + j][eA + 32] = fmaxf(acc[32 + j], 0.f);
        }
        __syncthreads();
        float acc2[64];
        {
            float b;
            #pragma unroll
            for (int j = 0; j < 32; j++) { b = s.b2[cg + j]; acc2[j] = b; acc2[32 + j] = b; }
        }
        gemm_half(s.Mid, s.W2, 0, eA, cg, acc2);
        {
            float* p0 = &g_u[(size_t)(base + eA) * HID + cg];
            #pragma unroll
            for (int j = 0; j < 8; j++) {
                float4 v = make_float4(fmaxf(acc2[4 * j + 0], 0.f), fmaxf(acc2[4 * j + 1], 0.f),
                                       fmaxf(acc2[4 * j + 2], 0.f), fmaxf(acc2[4 * j + 3], 0.f));
                *reinterpret_cast<float4*>(p0 + 4 * j) = v;
            }
            float* p1 = &g_u[(size_t)(base + eA + 32) * HID + cg];
            #pragma unroll
            for (int j = 0; j < 8; j++) {
                float4 v = make_float4(fmaxf(acc2[32 + 4 * j + 0], 0.f), fmaxf(acc2[32 + 4 * j + 1], 0.f),
                                       fmaxf(acc2[32 + 4 * j + 2], 0.f), fmaxf(acc2[32 + 4 * j + 3], 0.f));
                *reinterpret_cast<float4*>(p1 + 4 * j) = v;
            }
        }
    }
}

// ---------------- InstanceNorm: 64 blocks = (graph, 16-ch quad) ----------------
__global__ void instnorm_kernel() {
    int g = blockIdx.x >> 2, cq = (blockIdx.x & 3) << 4;
    int t = threadIdx.x;          // 512
    int c = t & 15, r = t >> 4;   // r 0..31
    const float* basep = g_u + (size_t)g * NS * HID + cq + c;
    float* outp = g_h + (size_t)g * NS * HID + cq + c;
    __shared__ float red[32][16];
    float s = 0.f;
    for (int n = r; n < NS; n += 32) s += basep[(size_t)n * HID];
    red[r][c] = s;
    __syncthreads();
    if (r == 0) {
        float tot = 0.f;
        #pragma unroll
        for (int i = 0; i < 32; i++) tot += red[i][c];
        red[0][c] = tot * (1.0f / NS);
    }
    __syncthreads();
    float mean = red[0][c];
    __syncthreads();
    float s2 = 0.f;
    for (int n = r; n < NS; n += 32) {
        float d = basep[(size_t)n * HID] - mean;
        s2 = fmaf(d, d, s2);
    }
    red[r][c] = s2;
    __syncthreads();
    if (r == 0) {
        float tot = 0.f;
        #pragma unroll
        for (int i = 0; i < 32; i++) tot += red[i][c];
        red[0][c] = rsqrtf(tot * (1.0f / NS) + EPSF);
    }
    __syncthreads();
    float inv = red[0][c];
    for (int n = r; n < NS; n += 32)
        outp[(size_t)n * HID] = (basep[(size_t)n * HID] - mean) * inv;
}

// ---------------- decoder ----------------
__global__ void decoder_kernel(const float* __restrict__ W, const float* __restrict__ b,
                               float* __restrict__ out) {
    __shared__ float sW[HID * 3];
    __shared__ float sb[3];
    int t = threadIdx.x;
    if (t < HID * 3) sW[t] = W[t];
    if (t < 3) sb[t] = b[t];
    __syncthreads();
    int n = blockIdx.x * 256 + t;
    float a0 = sb[0], a1 = sb[1], a2 = sb[2];
    const float* hr = g_h + (size_t)n * HID;
    #pragma unroll 8
    for (int k = 0; k < HID; k++) {
        float v = hr[k];
        a0 = fmaf(v, sW[k * 3 + 0], a0);
        a1 = fmaf(v, sW[k * 3 + 1], a1);
        a2 = fmaf(v, sW[k * 3 + 2], a2);
    }
    float inv = rsqrtf(a0 * a0 + a1 * a1 + a2 * a2);
    a0 *= inv; a1 *= inv; a2 *= inv;
    g_X[n * 3 + 0] = a0; g_X[n * 3 + 1] = a1; g_X[n * 3 + 2] = a2;
    out[1 + n * 3 + 0] = a0; out[1 + n * 3 + 1] = a1; out[1 + n * 3 + 2] = a2;
}

// ---------------- MMD kernels ----------------
__global__ void kxx_kernel() {
    int bid = blockIdx.x;
    int g = bid >> 8, tm = (bid >> 4) & 15, tn = bid & 15;
    const float* Xg = g_X + (size_t)g * NS * 3;
    __shared__ float ax[128][4];
    __shared__ float ay[128][4];
    __shared__ float rs[256];
    int t = threadIdx.x;
    for (int i = t; i < 128 * 3; i += 256) {
        int row = i / 3, col = i - row * 3;
        ax[row][col] = Xg[tm * 128 * 3 + i];
        ay[row][col] = Xg[tn * 128 * 3 + i];
    }
    __syncthreads();
    int r0 = (t >> 4) << 3, cb = (t & 15) << 3;
    float yv[8][3];
    #pragma unroll
    for (int j = 0; j < 8; j++) {
        yv[j][0] = ay[cb + j][0]; yv[j][1] = ay[cb + j][1]; yv[j][2] = ay[cb + j][2];
    }
    float s = 0.f;
    #pragma unroll
    for (int i = 0; i < 8; i++) {
        float x0 = ax[r0 + i][0], x1 = ax[r0 + i][1], x2 = ax[r0 + i][2];
        #pragma unroll
        for (int j = 0; j < 8; j++) {
            float d = fmaf(x0, yv[j][0], fmaf(x1, yv[j][1], x2 * yv[j][2]));
            s += fexp(fmaf(2.f, d, -2.f));
        }
    }
    rs[t] = s;
    __syncthreads();
    for (int o = 128; o > 0; o >>= 1) { if (t < o) rs[t] += rs[t + o]; __syncthreads(); }
    if (t == 0) atomicAdd(&g_acc[g], rs[0]);
}

__global__ void kxy_kernel() {
    __shared__ float sy[64][4];
    __shared__ float rs[256];
    int t = threadIdx.x;
    int n = blockIdx.x * 256 + t;
    for (int i = t; i < 64 * 3; i += 256) { int row = i / 3; sy[row][i - row * 3] = g_Y[i]; }
    __syncthreads();
    float x0 = g_X[n * 3], x1 = g_X[n * 3 + 1], x2 = g_X[n * 3 + 2];
    float s = 0.f;
    #pragma unroll 8
    for (int j = 0; j < 64; j++) {
        float d = fmaf(x0, sy[j][0], fmaf(x1, sy[j][1], x2 * sy[j][2]));
        s += fexp(fmaf(2.f, d, -2.f));
    }
    rs[t] = s;
    __syncthreads();
    for (int o = 128; o > 0; o >>= 1) { if (t < o) rs[t] += rs[t + o]; __syncthreads(); }
    if (t == 0) atomicAdd(&g_acc[NBATCH + (n >> 11)], rs[0]);
}

__global__ void finalize_kernel(float* __restrict__ out) {
    __shared__ float rs[64];
    int t = threadIdx.x;
    float x0 = g_Y[t * 3], x1 = g_Y[t * 3 + 1], x2 = g_Y[t * 3 + 2];
    float s = 0.f;
    for (int j = 0; j < 64; j++) {
        float d = fmaf(x0, g_Y[j * 3], fmaf(x1, g_Y[j * 3 + 1], x2 * g_Y[j * 3 + 2]));
        s += fexp(fmaf(2.f, d, -2.f));
    }
    rs[t] = s;
    __syncthreads();
    if (t == 0) {
        float kyy = 0.f;
        for (int j = 0; j < 64; j++) kyy += rs[j];
        kyy *= (1.0f / (64.f * 64.f));
        float loss = 0.f;
        for (int b = 0; b < NBATCH; b++) {
            float kxx = g_acc[b] * (1.0f / ((float)NS * (float)NS));
            float kxy = g_acc[NBATCH + b] * (1.0f / ((float)NS * 64.f));
            loss += kxx - 2.f * kxy + kyy;
        }
        out[0] = loss * (1.0f / NBATCH);
    }
}

// ---------------- launch ----------------
extern "C" void kernel_launch(void* const* d_in, const int* in_sizes, int n_in,
                              void* d_out, int out_size) {
    const float* x    = (const float*)d_in[0];
    const int*   esrc = (const int*)d_in[1];
    const int*   edst = (const int*)d_in[2];
    const float* encW = (const float*)d_in[4];
    const float* encb = (const float*)d_in[5];
    const float* m1W  = (const float*)d_in[6];
    const float* m1b  = (const float*)d_in[7];
    const float* m2W  = (const float*)d_in[8];
    const float* m2b  = (const float*)d_in[9];
    const float* u1W  = (const float*)d_in[10];
    const float* u1b  = (const float*)d_in[11];
    const float* u2W  = (const float*)d_in[12];
    const float* u2b  = (const float*)d_in[13];
    const float* decW = (const float*)d_in[14];
    const float* decb = (const float*)d_in[15];
    float* out = (float*)d_out;

    cudaFuncSetAttribute((const void*)edge_mlp_kernel,
                         cudaFuncAttributeMaxDynamicSharedMemorySize, (int)sizeof(SmemG));
    cudaFuncSetAttribute((const void*)node_mlp_kernel,
                         cudaFuncAttributeMaxDynamicSharedMemorySize, (int)sizeof(SmemG));

    compute_Y_kernel<<<1, 64>>>();
    encoder_kernel<<<NNODES * HID / 256, 256>>>(x, encW, encb);

    for (int l = 0; l < 4; l++) {
        zero_agg_kernel<<<NNODES * HID / 1024, 256>>>();
        edge_mlp_kernel<<<148, 256, sizeof(SmemG)>>>(
            m1W + (size_t)l * HID2 * HID, m1b + (size_t)l * HID,
            m2W + (size_t)l * HID * HID,  m2b + (size_t)l * HID, esrc, edst);
        node_mlp_kernel<<<128, 256, sizeof(SmemG)>>>(
            u1W + (size_t)l * HID2 * HID, u1b + (size_t)l * HID,
            u2W + (size_t)l * HID * HID,  u2b + (size_t)l * HID);
        instnorm_kernel<<<64, 512>>>();
    }

    zero_acc_kernel<<<1, 32>>>();
    decoder_kernel<<<NNODES / 256, 256>>>(decW, decb, out);
    kxy_kernel<<<NNODES / 256, 256>>>();
    kxx_kernel<<<NBATCH * 16 * 16, 256>>>();
    finalize_kernel<<<1, 64>>>(out);
}

// round 4
// speedup vs baseline: 1.2852x; 1.0384x over previous
#include <cuda_runtime.h>
#include <math.h>

#define NNODES 32768
#define NBATCH 16
#define NS 2048
#define HID 64
#define HID2 128
#define ETOT 524288
#define TE 256
#define NT 512
#define EPSF 1e-5f

// ---------------- scratch ----------------
__device__ float g_h[NNODES * HID];
__device__ float g_agg[NNODES * HID];
__device__ float g_u[NNODES * HID];
__device__ float g_X[NNODES * 3];
__device__ float g_Y[64 * 3];
__device__ float g_acc[2 * NBATCH];

// ---------------- smem for fused 2-layer MLP ----------------
struct SmemG {
    float W1[HID2][HID];   // 32 KB
    float W2[HID][HID];    // 16 KB
    float b1[HID];
    float b2[HID];
    float In[HID][TE];     // K-half staging, [k][e], 64 KB
    float Mid[HID][TE];    // 64 KB
    int   dst[TE];
    int   src[TE];
};

// fast exp, FFMA-only
__device__ __forceinline__ float fexp(float x) {
    const float L2E = 1.4426950408889634f;
    float t = fmaf(x, L2E, 12582912.0f);
    float kf = t - 12582912.0f;
    float f = fmaf(x, L2E, -kf);
    float p = 1.33335581e-3f;
    p = fmaf(p, f, 9.61812911e-3f);
    p = fmaf(p, f, 5.55041087e-2f);
    p = fmaf(p, f, 2.40226507e-1f);
    p = fmaf(p, f, 6.93147181e-1f);
    p = fmaf(p, f, 1.0f);
    int ik = (int)kf;
    return __int_as_float(__float_as_int(p) + (ik << 23));
}

__global__ void compute_Y_kernel() {
    int i = threadIdx.x;
    if (i < 64) {
        double phi = 3.14159265358979323846 * (3.0 - sqrt(5.0));
        double y = 1.0 - 2.0 * (double)i / 63.0;
        double r = sqrt(fmax(0.0, 1.0 - y * y));
        double th = phi * (double)i;
        g_Y[i * 3 + 0] = (float)(cos(th) * r);
        g_Y[i * 3 + 1] = (float)y;
        g_Y[i * 3 + 2] = (float)(sin(th) * r);
    }
}

__global__ void zero_agg_kernel() {
    int i = blockIdx.x * blockDim.x + threadIdx.x;
    reinterpret_cast<float4*>(g_agg)[i] = make_float4(0.f, 0.f, 0.f, 0.f);
}

__global__ void zero_acc_kernel() {
    int i = threadIdx.x;
    if (i < 2 * NBATCH) g_acc[i] = 0.f;
}

__global__ void encoder_kernel(const float* __restrict__ x,
                               const float* __restrict__ W,
                               const float* __restrict__ b) {
    __shared__ float sW[3 * HID];
    __shared__ float sb[HID];
    int t = threadIdx.x;
    if (t < 3 * HID) sW[t] = W[t];
    if (t < HID) sb[t] = b[t];
    __syncthreads();
    int idx = blockIdx.x * 256 + t;
    int n = idx >> 6, c = idx & 63;
    float x0 = x[n * 3 + 0], x1 = x[n * 3 + 1], x2 = x[n * 3 + 2];
    g_h[idx] = fmaf(x0, sW[c], fmaf(x1, sW[HID + c], fmaf(x2, sW[2 * HID + c], sb[c])));
}

// ======== GEMM core: thread = 2 edges (eA, eA+128) x 16 cols, W broadcast ========
// acc[0..15] = edge eA, acc[16..31] = edge eA+128, cols cg..cg+15
__device__ __forceinline__ void gemm_half(const float (*In)[TE], const float (*W)[HID],
                                          int koff, int eA, int cg, float* acc) {
    #pragma unroll 4
    for (int kk = 0; kk < 64; kk++) {
        float a0 = In[kk][eA];
        float a1 = In[kk][eA + 128];
        const float4* w4 = reinterpret_cast<const float4*>(&W[koff + kk][cg]);
        #pragma unroll
        for (int j = 0; j < 4; j++) {
            float4 w = w4[j];
            acc[4 * j + 0] = fmaf(a0, w.x, acc[4 * j + 0]);
            acc[4 * j + 1] = fmaf(a0, w.y, acc[4 * j + 1]);
            acc[4 * j + 2] = fmaf(a0, w.z, acc[4 * j + 2]);
            acc[4 * j + 3] = fmaf(a0, w.w, acc[4 * j + 3]);
            acc[16 + 4 * j + 0] = fmaf(a1, w.x, acc[16 + 4 * j + 0]);
            acc[16 + 4 * j + 1] = fmaf(a1, w.y, acc[16 + 4 * j + 1]);
            acc[16 + 4 * j + 2] = fmaf(a1, w.z, acc[16 + 4 * j + 2]);
            acc[16 + 4 * j + 3] = fmaf(a1, w.w, acc[16 + 4 * j + 3]);
        }
    }
}

// gather a TE-edge tile of 64-float rows into In[k][e]; 512 threads, 2 threads/row
__device__ __forceinline__ void gather_rows(float (*In)[TE], const float* __restrict__ src,
                                            const int* idx, int t) {
    int e = t & 255;
    int qb = (t >> 8) * 8;                          // quads qb..qb+7
    const float4* hp = reinterpret_cast<const float4*>(src) + (size_t)idx[e] * 16 + qb;
    #pragma unroll
    for (int q = 0; q < 8; q++) {
        float4 v = hp[q];
        int k = (qb + q) * 4;
        In[k + 0][e] = v.x; In[k + 1][e] = v.y;
        In[k + 2][e] = v.z; In[k + 3][e] = v.w;
    }
}

__device__ __forceinline__ void gather_seq(float (*In)[TE], const float* __restrict__ src,
                                           int base, int t) {
    int e = t & 255;
    int qb = (t >> 8) * 8;
    const float4* hp = reinterpret_cast<const float4*>(src) + (size_t)(base + e) * 16 + qb;
    #pragma unroll
    for (int q = 0; q < 8; q++) {
        float4 v = hp[q];
        int k = (qb + q) * 4;
        In[k + 0][e] = v.x; In[k + 1][e] = v.y;
        In[k + 2][e] = v.z; In[k + 3][e] = v.w;
    }
}

// ---------------- edge MLP ----------------
__global__ void __launch_bounds__(NT, 1) edge_mlp_kernel(
    const float* __restrict__ W1g, const float* __restrict__ b1g,
    const float* __restrict__ W2g, const float* __restrict__ b2g,
    const int* __restrict__ esrc, const int* __restrict__ edst) {
    extern __shared__ char sraw[];
    SmemG& s = *reinterpret_cast<SmemG*>(sraw);
    const int t = threadIdx.x;
    for (int i = t; i < HID2 * HID; i += NT) (&s.W1[0][0])[i] = W1g[i];
    for (int i = t; i < HID * HID; i += NT) (&s.W2[0][0])[i] = W2g[i];
    if (t < HID) { s.b1[t] = b1g[t]; s.b2[t] = b2g[t]; }
    const int lane = t & 31, wid = t >> 5;          // 16 warps
    const int cg = (wid & 3) * 16;                  // 16-col slab
    const int eA = (wid >> 2) * 32 + lane;          // edges eA, eA+128
    const int ntiles = ETOT / TE;
    for (int tile = blockIdx.x; tile < ntiles; tile += gridDim.x) {
        const int base = tile * TE;
        __syncthreads();                             // prev tile done
        if (t < TE) { s.dst[t] = edst[base + t]; s.src[t] = esrc[base + t]; }
        __syncthreads();
        gather_rows(s.In, g_h, s.dst, t);            // half 0: h[dst]
        __syncthreads();
        float acc[32];
        #pragma unroll
        for (int j = 0; j < 16; j++) { float b = s.b1[cg + j]; acc[j] = b; acc[16 + j] = b; }
        gemm_half(s.In, s.W1, 0, eA, cg, acc);
        __syncthreads();                             // done reading half 0
        gather_rows(s.In, g_h, s.src, t);            // half 1: h[src]
        __syncthreads();
        gemm_half(s.In, s.W1, 64, eA, cg, acc);
        #pragma unroll
        for (int j = 0; j < 16; j++) {
            s.Mid[cg + j][eA]       = fmaxf(acc[j], 0.f);
            s.Mid[cg + j][eA + 128] = fmaxf(acc[16 + j], 0.f);
        }
        __syncthreads();
        float acc2[32];
        #pragma unroll
        for (int j = 0; j < 16; j++) { float b = s.b2[cg + j]; acc2[j] = b; acc2[16 + j] = b; }
        gemm_half(s.Mid, s.W2, 0, eA, cg, acc2);
        {
            float* p0 = &g_agg[(size_t)s.dst[eA] * HID + cg];
            #pragma unroll
            for (int j = 0; j < 4; j++) {
                float v0 = fmaxf(acc2[4 * j + 0], 0.f), v1 = fmaxf(acc2[4 * j + 1], 0.f);
                float v2 = fmaxf(acc2[4 * j + 2], 0.f), v3 = fmaxf(acc2[4 * j + 3], 0.f);
                asm volatile("red.global.add.v4.f32 [%0], {%1,%2,%3,%4};"
                             :: "l"(p0 + 4 * j), "f"(v0), "f"(v1), "f"(v2), "f"(v3) : "memory");
            }
            float* p1 = &g_agg[(size_t)s.dst[eA + 128] * HID + cg];
            #pragma unroll
            for (int j = 0; j < 4; j++) {
                float v0 = fmaxf(acc2[16 + 4 * j + 0], 0.f), v1 = fmaxf(acc2[16 + 4 * j + 1], 0.f);
                float v2 = fmaxf(acc2[16 + 4 * j + 2], 0.f), v3 = fmaxf(acc2[16 + 4 * j + 3], 0.f);
                asm volatile("red.global.add.v4.f32 [%0], {%1,%2,%3,%4};"
                             :: "l"(p1 + 4 * j), "f"(v0), "f"(v1), "f"(v2), "f"(v3) : "memory");
            }
        }
    }
}

// ---------------- node MLP ----------------
__global__ void __launch_bounds__(NT, 1) node_mlp_kernel(
    const float* __restrict__ W1g, const float* __restrict__ b1g,
    const float* __restrict__ W2g, const float* __restrict__ b2g) {
    extern __shared__ char sraw[];
    SmemG& s = *reinterpret_cast<SmemG*>(sraw);
    const int t = threadIdx.x;
    for (int i = t; i < HID2 * HID; i += NT) (&s.W1[0][0])[i] = W1g[i];
    for (int i = t; i < HID * HID; i += NT) (&s.W2[0][0])[i] = W2g[i];
    if (t < HID) { s.b1[t] = b1g[t]; s.b2[t] = b2g[t]; }
    const int lane = t & 31, wid = t >> 5;
    const int cg = (wid & 3) * 16;
    const int eA = (wid >> 2) * 32 + lane;
    const int ntiles = NNODES / TE;
    for (int tile = blockIdx.x; tile < ntiles; tile += gridDim.x) {
        const int base = tile * TE;
        __syncthreads();
        gather_seq(s.In, g_h, base, t);              // half 0: h
        __syncthreads();
        float acc[32];
        #pragma unroll
        for (int j = 0; j < 16; j++) { float b = s.b1[cg + j]; acc[j] = b; acc[16 + j] = b; }
        gemm_half(s.In, s.W1, 0, eA, cg, acc);
        __syncthreads();
        gather_seq(s.In, g_agg, base, t);            // half 1: agg
        __syncthreads();
        gemm_half(s.In, s.W1, 64, eA, cg, acc);
        #pragma unroll
        for (int j = 0; j < 16; j++) {
            s.Mid[cg + j][eA]       = fmaxf(acc[j], 0.f);
            s.Mid[cg + j][eA + 128] = fmaxf(acc[16 + j], 0.f);
        }
        __syncthreads();
        float acc2[32];
        #pragma unroll
        for (int j = 0; j < 16; j++) { float b = s.b2[cg + j]; acc2[j] = b; acc2[16 + j] = b; }
        gemm_half(s.Mid, s.W2, 0, eA, cg, acc2);
        {
            float* p0 = &g_u[(size_t)(base + eA) * HID + cg];
            #pragma unroll
            for (int j = 0; j < 4; j++) {
                float4 v = make_float4(fmaxf(acc2[4 * j + 0], 0.f), fmaxf(acc2[4 * j + 1], 0.f),
                                       fmaxf(acc2[4 * j + 2], 0.f), fmaxf(acc2[4 * j + 3], 0.f));
                *reinterpret_cast<float4*>(p0 + 4 * j) = v;
            }
            float* p1 = &g_u[(size_t)(base + eA + 128) * HID + cg];
            #pragma unroll
            for (int j = 0; j < 4; j++) {
                float4 v = make_float4(fmaxf(acc2[16 + 4 * j + 0], 0.f), fmaxf(acc2[16 + 4 * j + 1], 0.f),
                                       fmaxf(acc2[16 + 4 * j + 2], 0.f), fmaxf(acc2[16 + 4 * j + 3], 0.f));
                *reinterpret_cast<float4*>(p1 + 4 * j) = v;
            }
        }
    }
}

// ---------------- InstanceNorm: 64 blocks = (graph, 16-ch quad) ----------------
__global__ void instnorm_kernel() {
    int g = blockIdx.x >> 2, cq = (blockIdx.x & 3) << 4;
    int t = threadIdx.x;          // 512
    int c = t & 15, r = t >> 4;   // r 0..31
    const float* basep = g_u + (size_t)g * NS * HID + cq + c;
    float* outp = g_h + (size_t)g * NS * HID + cq + c;
    __shared__ float red[32][16];
    float s = 0.f;
    for (int n = r; n < NS; n += 32) s += basep[(size_t)n * HID];
    red[r][c] = s;
    __syncthreads();
    if (r == 0) {
        float tot = 0.f;
        #pragma unroll
        for (int i = 0; i < 32; i++) tot += red[i][c];
        red[0][c] = tot * (1.0f / NS);
    }
    __syncthreads();
    float mean = red[0][c];
    __syncthreads();
    float s2 = 0.f;
    for (int n = r; n < NS; n += 32) {
        float d = basep[(size_t)n * HID] - mean;
        s2 = fmaf(d, d, s2);
    }
    red[r][c] = s2;
    __syncthreads();
    if (r == 0) {
        float tot = 0.f;
        #pragma unroll
        for (int i = 0; i < 32; i++) tot += red[i][c];
        red[0][c] = rsqrtf(tot * (1.0f / NS) + EPSF);
    }
    __syncthreads();
    float inv = red[0][c];
    for (int n = r; n < NS; n += 32)
        outp[(size_t)n * HID] = (basep[(size_t)n * HID] - mean) * inv;
}

// ---------------- decoder ----------------
__global__ void decoder_kernel(const float* __restrict__ W, const float* __restrict__ b,
                               float* __restrict__ out) {
    __shared__ float sW[HID * 3];
    __shared__ float sb[3];
    int t = threadIdx.x;
    if (t < HID * 3) sW[t] = W[t];
    if (t < 3) sb[t] = b[t];
    __syncthreads();
    int n = blockIdx.x * 256 + t;
    float a0 = sb[0], a1 = sb[1], a2 = sb[2];
    const float* hr = g_h + (size_t)n * HID;
    #pragma unroll 8
    for (int k = 0; k < HID; k++) {
        float v = hr[k];
        a0 = fmaf(v, sW[k * 3 + 0], a0);
        a1 = fmaf(v, sW[k * 3 + 1], a1);
        a2 = fmaf(v, sW[k * 3 + 2], a2);
    }
    float inv = rsqrtf(a0 * a0 + a1 * a1 + a2 * a2);
    a0 *= inv; a1 *= inv; a2 *= inv;
    g_X[n * 3 + 0] = a0; g_X[n * 3 + 1] = a1; g_X[n * 3 + 2] = a2;
    out[1 + n * 3 + 0] = a0; out[1 + n * 3 + 1] = a1; out[1 + n * 3 + 2] = a2;
}

// ---------------- MMD kernels ----------------
__global__ void kxx_kernel() {
    int bid = blockIdx.x;
    int g = bid >> 8, tm = (bid >> 4) & 15, tn = bid & 15;
    const float* Xg = g_X + (size_t)g * NS * 3;
    __shared__ float ax[128][4];
    __shared__ float ay[128][4];
    __shared__ float rs[256];
    int t = threadIdx.x;
    for (int i = t; i < 128 * 3; i += 256) {
        int row = i / 3, col = i - row * 3;
        ax[row][col] = Xg[tm * 128 * 3 + i];
        ay[row][col] = Xg[tn * 128 * 3 + i];
    }
    __syncthreads();
    int r0 = (t >> 4) << 3, cb = (t & 15) << 3;
    float yv[8][3];
    #pragma unroll
    for (int j = 0; j < 8; j++) {
        yv[j][0] = ay[cb + j][0]; yv[j][1] = ay[cb + j][1]; yv[j][2] = ay[cb + j][2];
    }
    float s = 0.f;
    #pragma unroll
    for (int i = 0; i < 8; i++) {
        float x0 = ax[r0 + i][0], x1 = ax[r0 + i][1], x2 = ax[r0 + i][2];
        #pragma unroll
        for (int j = 0; j < 8; j++) {
            float d = fmaf(x0, yv[j][0], fmaf(x1, yv[j][1], x2 * yv[j][2]));
            s += fexp(fmaf(2.f, d, -2.f));
        }
    }
    rs[t] = s;
    __syncthreads();
    for (int o = 128; o > 0; o >>= 1) { if (t < o) rs[t] += rs[t + o]; __syncthreads(); }
    if (t == 0) atomicAdd(&g_acc[g], rs[0]);
}

__global__ void kxy_kernel() {
    __shared__ float sy[64][4];
    __shared__ float rs[256];
    int t = threadIdx.x;
    int n = blockIdx.x * 256 + t;
    for (int i = t; i < 64 * 3; i += 256) { int row = i / 3; sy[row][i - row * 3] = g_Y[i]; }
    __syncthreads();
    float x0 = g_X[n * 3], x1 = g_X[n * 3 + 1], x2 = g_X[n * 3 + 2];
    float s = 0.f;
    #pragma unroll 8
    for (int j = 0; j < 64; j++) {
        float d = fmaf(x0, sy[j][0], fmaf(x1, sy[j][1], x2 * sy[j][2]));
        s += fexp(fmaf(2.f, d, -2.f));
    }
    rs[t] = s;
    __syncthreads();
    for (int o = 128; o > 0; o >>= 1) { if (t < o) rs[t] += rs[t + o]; __syncthreads(); }
    if (t == 0) atomicAdd(&g_acc[NBATCH + (n >> 11)], rs[0]);
}

__global__ void finalize_kernel(float* __restrict__ out) {
    __shared__ float rs[64];
    int t = threadIdx.x;
    float x0 = g_Y[t * 3], x1 = g_Y[t * 3 + 1], x2 = g_Y[t * 3 + 2];
    float s = 0.f;
    for (int j = 0; j < 64; j++) {
        float d = fmaf(x0, g_Y[j * 3], fmaf(x1, g_Y[j * 3 + 1], x2 * g_Y[j * 3 + 2]));
        s += fexp(fmaf(2.f, d, -2.f));
    }
    rs[t] = s;
    __syncthreads();
    if (t == 0) {
        float kyy = 0.f;
        for (int j = 0; j < 64; j++) kyy += rs[j];
        kyy *= (1.0f / (64.f * 64.f));
        float loss = 0.f;
        for (int b = 0; b < NBATCH; b++) {
            float kxx = g_acc[b] * (1.0f / ((float)NS * (float)NS));
            float kxy = g_acc[NBATCH + b] * (1.0f / ((float)NS * 64.f));
            loss += kxx - 2.f * kxy + kyy;
        }
        out[0] = loss * (1.0f / NBATCH);
    }
}

// ---------------- launch ----------------
extern "C" void kernel_launch(void* const* d_in, const int* in_sizes, int n_in,
                              void* d_out, int out_size) {
    const float* x    = (const float*)d_in[0];
    const int*   esrc = (const int*)d_in[1];
    const int*   edst = (const int*)d_in[2];
    const float* encW = (const float*)d_in[4];
    const float* encb = (const float*)d_in[5];
    const float* m1W  = (const float*)d_in[6];
    const float* m1b  = (const float*)d_in[7];
    const float* m2W  = (const float*)d_in[8];
    const float* m2b  = (const float*)d_in[9];
    const float* u1W  = (const float*)d_in[10];
    const float* u1b  = (const float*)d_in[11];
    const float* u2W  = (const float*)d_in[12];
    const float* u2b  = (const float*)d_in[13];
    const float* decW = (const float*)d_in[14];
    const float* decb = (const float*)d_in[15];
    float* out = (float*)d_out;

    cudaFuncSetAttribute((const void*)edge_mlp_kernel,
                         cudaFuncAttributeMaxDynamicSharedMemorySize, (int)sizeof(SmemG));
    cudaFuncSetAttribute((const void*)node_mlp_kernel,
                         cudaFuncAttributeMaxDynamicSharedMemorySize, (int)sizeof(SmemG));

    compute_Y_kernel<<<1, 64>>>();
    encoder_kernel<<<NNODES * HID / 256, 256>>>(x, encW, encb);

    for (int l = 0; l < 4; l++) {
        zero_agg_kernel<<<NNODES * HID / 1024, 256>>>();
        edge_mlp_kernel<<<148, NT, sizeof(SmemG)>>>(
            m1W + (size_t)l * HID2 * HID, m1b + (size_t)l * HID,
            m2W + (size_t)l * HID * HID,  m2b + (size_t)l * HID, esrc, edst);
        node_mlp_kernel<<<128, NT, sizeof(SmemG)>>>(
            u1W + (size_t)l * HID2 * HID, u1b + (size_t)l * HID,
            u2W + (size_t)l * HID * HID,  u2b + (size_t)l * HID);
        instnorm_kernel<<<64, 512>>>();
    }

    zero_acc_kernel<<<1, 32>>>();
    decoder_kernel<<<NNODES / 256, 256>>>(decW, decb, out);
    kxy_kernel<<<NNODES / 256, 256>>>();
    kxx_kernel<<<NBATCH * 16 * 16, 256>>>();
    finalize_kernel<<<1, 64>>>(out);
}

// round 6
// speedup vs baseline: 2.2429x; 1.7452x over previous
#include <cuda_runtime.h>
#include <cuda_bf16.h>
#include <math.h>
#include <stdint.h>

#define NNODES 32768
#define NBATCH 16
#define NS 2048
#define HID 64
#define ETOT 524288
#define TM 128
#define EPSF 1e-5f

// ---------------- scratch ----------------
__device__ float g_h[NNODES * HID];
__device__ float g_agg[NNODES * HID];
__device__ float g_u[NNODES * HID];
__device__ float g_X[NNODES * 3];
__device__ float g_Y[64 * 3];
__device__ float g_acc[2 * NBATCH];

// ---------------- smem layout (bytes). Rows padded +16B for conflict-free ldmatrix ----
// A   [128][136] bf16 (stride 272B)  ; B1 = W1^T [64][136] ; Mid [128][72] (144B) ; B2 [64][72]
#define A_HI   0
#define A_LO   34816
#define B1_HI  69632
#define B1_LO  87040
#define MID_HI 104448
#define MID_LO 122880
#define B2_HI  141312
#define B2_LO  150528
#define BIAS1  159744
#define BIAS2  160000
#define DSTO   160256
#define SRCO   160768
#define SMEM_MMA_BYTES 161280

static __device__ __forceinline__ uint32_t cvta_smem(const void* p) {
    uint32_t a;
    asm("{ .reg .u64 t; cvta.to.shared.u64 t, %1; cvt.u32.u64 %0, t; }" : "=r"(a) : "l"(p));
    return a;
}
static __device__ __forceinline__ void ldsm4(uint32_t* r, uint32_t addr) {
    asm volatile("ldmatrix.sync.aligned.m8n8.x4.shared.b16 {%0,%1,%2,%3}, [%4];"
                 : "=r"(r[0]), "=r"(r[1]), "=r"(r[2]), "=r"(r[3]) : "r"(addr));
}
static __device__ __forceinline__ void mma_bf16(float* c, const uint32_t* a, const uint32_t* b) {
    asm volatile(
        "mma.sync.aligned.m16n8k16.row.col.f32.bf16.bf16.f32 "
        "{%0,%1,%2,%3}, {%4,%5,%6,%7}, {%8,%9}, {%0,%1,%2,%3};"
        : "+f"(c[0]), "+f"(c[1]), "+f"(c[2]), "+f"(c[3])
        : "r"(a[0]), "r"(a[1]), "r"(a[2]), "r"(a[3]), "r"(b[0]), "r"(b[1]));
}

// split 8 floats into bf16 hi/lo packed words
static __device__ __forceinline__ void split8(const float* f, uint4& hi, uint4& lo) {
    uint32_t hw[4], lw[4];
    #pragma unroll
    for (int j = 0; j < 4; j++) {
        __nv_bfloat16 h0 = __float2bfloat16(f[2 * j]);
        __nv_bfloat16 h1 = __float2bfloat16(f[2 * j + 1]);
        float r0 = f[2 * j] - __bfloat162float(h0);
        float r1 = f[2 * j + 1] - __bfloat162float(h1);
        __nv_bfloat16 l0 = __float2bfloat16(r0);
        __nv_bfloat16 l1 = __float2bfloat16(r1);
        hw[j] = ((uint32_t)__bfloat16_as_ushort(h1) << 16) | (uint32_t)__bfloat16_as_ushort(h0);
        lw[j] = ((uint32_t)__bfloat16_as_ushort(l1) << 16) | (uint32_t)__bfloat16_as_ushort(l0);
    }
    hi = make_uint4(hw[0], hw[1], hw[2], hw[3]);
    lo = make_uint4(lw[0], lw[1], lw[2], lw[3]);
}
static __device__ __forceinline__ void split2(float x, float y, uint32_t& hi, uint32_t& lo) {
    __nv_bfloat16 hx = __float2bfloat16(x), hy = __float2bfloat16(y);
    __nv_bfloat16 lx = __float2bfloat16(x - __bfloat162float(hx));
    __nv_bfloat16 ly = __float2bfloat16(y - __bfloat162float(hy));
    hi = ((uint32_t)__bfloat16_as_ushort(hy) << 16) | (uint32_t)__bfloat16_as_ushort(hx);
    lo = ((uint32_t)__bfloat16_as_ushort(ly) << 16) | (uint32_t)__bfloat16_as_ushort(lx);
}

// fast exp, FFMA-only
__device__ __forceinline__ float fexp(float x) {
    const float L2E = 1.4426950408889634f;
    float t = fmaf(x, L2E, 12582912.0f);
    float kf = t - 12582912.0f;
    float f = fmaf(x, L2E, -kf);
    float p = 1.33335581e-3f;
    p = fmaf(p, f, 9.61812911e-3f);
    p = fmaf(p, f, 5.55041087e-2f);
    p = fmaf(p, f, 2.40226507e-1f);
    p = fmaf(p, f, 6.93147181e-1f);
    p = fmaf(p, f, 1.0f);
    int ik = (int)kf;
    return __int_as_float(__float_as_int(p) + (ik << 23));
}

__global__ void compute_Y_kernel() {
    int i = threadIdx.x;
    if (i < 64) {
        double phi = 3.14159265358979323846 * (3.0 - sqrt(5.0));
        double y = 1.0 - 2.0 * (double)i / 63.0;
        double r = sqrt(fmax(0.0, 1.0 - y * y));
        double th = phi * (double)i;
        g_Y[i * 3 + 0] = (float)(cos(th) * r);
        g_Y[i * 3 + 1] = (float)y;
        g_Y[i * 3 + 2] = (float)(sin(th) * r);
    }
}

__global__ void zero_agg_kernel() {
    int i = blockIdx.x * blockDim.x + threadIdx.x;
    reinterpret_cast<float4*>(g_agg)[i] = make_float4(0.f, 0.f, 0.f, 0.f);
}

__global__ void zero_acc_kernel() {
    int i = threadIdx.x;
    if (i < 2 * NBATCH) g_acc[i] = 0.f;
}

__global__ void encoder_kernel(const float* __restrict__ x,
                               const float* __restrict__ W,
                               const float* __restrict__ b) {
    __shared__ float sW[3 * HID];
    __shared__ float sb[HID];
    int t = threadIdx.x;
    if (t < 3 * HID) sW[t] = W[t];
    if (t < HID) sb[t] = b[t];
    __syncthreads();
    int idx = blockIdx.x * 256 + t;
    int n = idx >> 6, c = idx & 63;
    float x0 = x[n * 3 + 0], x1 = x[n * 3 + 1], x2 = x[n * 3 + 2];
    g_h[idx] = fmaf(x0, sW[c], fmaf(x1, sW[HID + c], fmaf(x2, sW[2 * HID + c], sb[c])));
}

// ============ warp-MMA fused 2-layer MLP (EDGE: gather+scatter; else sequential) ============
template <bool EDGE>
__global__ void __launch_bounds__(256, 1) mlp_mma_kernel(
    const float* __restrict__ W1g, const float* __restrict__ b1g,
    const float* __restrict__ W2g, const float* __restrict__ b2g,
    const int* __restrict__ esrc, const int* __restrict__ edst) {
    extern __shared__ char sp[];
    const uint32_t sb = cvta_smem(sp);
    const int t = threadIdx.x, lane = t & 31, wid = t >> 5;

    float* b1v = reinterpret_cast<float*>(sp + BIAS1);
    float* b2v = reinterpret_cast<float*>(sp + BIAS2);
    int* dstA = reinterpret_cast<int*>(sp + DSTO);
    int* srcA = reinterpret_cast<int*>(sp + SRCO);

    // ---- weights: B1 = W1^T [64 n][136 k pad] bf16 hi/lo ; B2 = W2^T [64][72] ----
    for (int i = t; i < 128 * 64; i += 256) {
        int k = i >> 6, n = i & 63;
        float w = W1g[i];
        __nv_bfloat16 hi = __float2bfloat16(w);
        __nv_bfloat16 lo = __float2bfloat16(w - __bfloat162float(hi));
        reinterpret_cast<__nv_bfloat16*>(sp + B1_HI)[n * 136 + k] = hi;
        reinterpret_cast<__nv_bfloat16*>(sp + B1_LO)[n * 136 + k] = lo;
    }
    for (int i = t; i < 64 * 64; i += 256) {
        int k = i >> 6, n = i & 63;
        float w = W2g[i];
        __nv_bfloat16 hi = __float2bfloat16(w);
        __nv_bfloat16 lo = __float2bfloat16(w - __bfloat162float(hi));
        reinterpret_cast<__nv_bfloat16*>(sp + B2_HI)[n * 72 + k] = hi;
        reinterpret_cast<__nv_bfloat16*>(sp + B2_LO)[n * 72 + k] = lo;
    }
    if (t < 64) { b1v[t] = b1g[t]; b2v[t] = b2g[t]; }

    // per-thread fragment geometry
    const int g = lane >> 3;
    const int a_row = (g & 1) * 8 + (lane & 7);      // + m-tile base
    const int a_koff = (g >> 1) * 8;
    const int b_row = (g >> 1) * 8 + (lane & 7);
    const int b_koff = (g & 1) * 8;
    const int m0 = (wid & 3) * 32;
    const int n0 = (wid >> 2) * 32;
    const int er = lane >> 2, ec = lane & 3;         // epilogue row/colpair

    uint32_t aA[2], aB[2], aM[2], aB2[2];
    #pragma unroll
    for (int i = 0; i < 2; i++) {
        aA[i]  = sb + A_HI   + (uint32_t)(m0 + 16 * i + a_row) * 272 + a_koff * 2;
        aB[i]  = sb + B1_HI  + (uint32_t)(n0 + 16 * i + b_row) * 272 + b_koff * 2;
        aM[i]  = sb + MID_HI + (uint32_t)(m0 + 16 * i + a_row) * 144 + a_koff * 2;
        aB2[i] = sb + B2_HI  + (uint32_t)(n0 + 16 * i + b_row) * 144 + b_koff * 2;
    }

    const int ntiles = (EDGE ? ETOT : NNODES) / TM;
    for (int tile = blockIdx.x; tile < ntiles; tile += gridDim.x) {
        const int base = tile * TM;
        __syncthreads();                                  // prev tile fully done
        if (EDGE) {
            if (t < TM) dstA[t] = edst[base + t];
            else srcA[t - TM] = esrc[base + t - TM];
            __syncthreads();
        }
        // ---- gather + split into A (k 0-63 = dst/h, 64-127 = src/agg) ----
        #pragma unroll
        for (int i = t; i < 2048; i += 256) {
            int half = i >> 10, rem = i & 1023;
            int e = rem >> 3, c = rem & 7;
            const float* gs;
            int node;
            if (EDGE) { node = half ? srcA[e] : dstA[e]; gs = g_h; }
            else      { node = base + e; gs = half ? g_agg : g_h; }
            const float4* p4 = reinterpret_cast<const float4*>(gs + (size_t)node * HID + c * 8);
            float4 va = p4[0], vb = p4[1];
            float f[8] = {va.x, va.y, va.z, va.w, vb.x, vb.y, vb.z, vb.w};
            uint4 hi, lo;
            split8(f, hi, lo);
            uint32_t off = (uint32_t)e * 272 + half * 128 + c * 16;
            *reinterpret_cast<uint4*>(sp + A_HI + off) = hi;
            *reinterpret_cast<uint4*>(sp + A_LO + off) = lo;
        }
        __syncthreads();
        // ---- GEMM1: [128,64] = A[128,128] @ B1^T, 3-term bf16 split ----
        float acc[2][4][4];
        #pragma unroll
        for (int mt = 0; mt < 2; mt++)
            #pragma unroll
            for (int nt = 0; nt < 4; nt++)
                #pragma unroll
                for (int j = 0; j < 4; j++) acc[mt][nt][j] = 0.f;
        #pragma unroll
        for (int kk = 0; kk < 8; kk++) {
            uint32_t ah[2][4], al[2][4], bh[2][4], bl[2][4];
            #pragma unroll
            for (int i = 0; i < 2; i++) {
                ldsm4(ah[i], aA[i] + kk * 32);
                ldsm4(al[i], aA[i] + 34816 + kk * 32);
                ldsm4(bh[i], aB[i] + kk * 32);
                ldsm4(bl[i], aB[i] + 17408 + kk * 32);
            }
            #pragma unroll
            for (int mt = 0; mt < 2; mt++)
                #pragma unroll
                for (int nt = 0; nt < 4; nt++) {
                    const uint32_t* bhp = &bh[nt >> 1][(nt & 1) * 2];
                    const uint32_t* blp = &bl[nt >> 1][(nt & 1) * 2];
                    mma_bf16(acc[mt][nt], ah[mt], bhp);
                    mma_bf16(acc[mt][nt], al[mt], bhp);
                    mma_bf16(acc[mt][nt], ah[mt], blp);
                }
        }
        // ---- epilogue 1: bias+relu, split -> Mid ----
        #pragma unroll
        for (int mt = 0; mt < 2; mt++)
            #pragma unroll
            for (int nt = 0; nt < 4; nt++) {
                int r0 = m0 + 16 * mt + er, r1 = r0 + 8;
                int n = n0 + 8 * nt + 2 * ec;
                float v00 = fmaxf(acc[mt][nt][0] + b1v[n], 0.f);
                float v01 = fmaxf(acc[mt][nt][1] + b1v[n + 1], 0.f);
                float v10 = fmaxf(acc[mt][nt][2] + b1v[n], 0.f);
                float v11 = fmaxf(acc[mt][nt][3] + b1v[n + 1], 0.f);
                uint32_t h0, l0, h1, l1;
                split2(v00, v01, h0, l0);
                split2(v10, v11, h1, l1);
                int w0 = r0 * 36 + (n >> 1), w1 = r1 * 36 + (n >> 1);
                reinterpret_cast<uint32_t*>(sp + MID_HI)[w0] = h0;
                reinterpret_cast<uint32_t*>(sp + MID_LO)[w0] = l0;
                reinterpret_cast<uint32_t*>(sp + MID_HI)[w1] = h1;
                reinterpret_cast<uint32_t*>(sp + MID_LO)[w1] = l1;
            }
        __syncthreads();
        // ---- GEMM2: [128,64] = Mid[128,64] @ B2^T ----
        float acc2[2][4][4];
        #pragma unroll
        for (int mt = 0; mt < 2; mt++)
            #pragma unroll
            for (int nt = 0; nt < 4; nt++)
                #pragma unroll
                for (int j = 0; j < 4; j++) acc2[mt][nt][j] = 0.f;
        #pragma unroll
        for (int kk = 0; kk < 4; kk++) {
            uint32_t ah[2][4], al[2][4], bh[2][4], bl[2][4];
            #pragma unroll
            for (int i = 0; i < 2; i++) {
                ldsm4(ah[i], aM[i] + kk * 32);
                ldsm4(al[i], aM[i] + 18432 + kk * 32);
                ldsm4(bh[i], aB2[i] + kk * 32);
                ldsm4(bl[i], aB2[i] + 9216 + kk * 32);
            }
            #pragma unroll
            for (int mt = 0; mt < 2; mt++)
                #pragma unroll
                for (int nt = 0; nt < 4; nt++) {
                    const uint32_t* bhp = &bh[nt >> 1][(nt & 1) * 2];
                    const uint32_t* blp = &bl[nt >> 1][(nt & 1) * 2];
                    mma_bf16(acc2[mt][nt], ah[mt], bhp);
                    mma_bf16(acc2[mt][nt], al[mt], bhp);
                    mma_bf16(acc2[mt][nt], ah[mt], blp);
                }
        }
        // ---- epilogue 2: bias+relu -> scatter/store ----
        #pragma unroll
        for (int mt = 0; mt < 2; mt++)
            #pragma unroll
            for (int nt = 0; nt < 4; nt++) {
                int r0 = m0 + 16 * mt + er, r1 = r0 + 8;
                int n = n0 + 8 * nt + 2 * ec;
                float v00 = fmaxf(acc2[mt][nt][0] + b2v[n], 0.f);
                float v01 = fmaxf(acc2[mt][nt][1] + b2v[n + 1], 0.f);
                float v10 = fmaxf(acc2[mt][nt][2] + b2v[n], 0.f);
                float v11 = fmaxf(acc2[mt][nt][3] + b2v[n + 1], 0.f);
                if (EDGE) {
                    float* p0 = g_agg + (size_t)dstA[r0] * HID + n;
                    float* p1 = g_agg + (size_t)dstA[r1] * HID + n;
                    asm volatile("red.global.add.v2.f32 [%0], {%1,%2};"
                                 :: "l"(p0), "f"(v00), "f"(v01) : "memory");
                    asm volatile("red.global.add.v2.f32 [%0], {%1,%2};"
                                 :: "l"(p1), "f"(v10), "f"(v11) : "memory");
                } else {
                    *reinterpret_cast<float2*>(g_u + (size_t)(base + r0) * HID + n) =
                        make_float2(v00, v01);
                    *reinterpret_cast<float2*>(g_u + (size_t)(base + r1) * HID + n) =
                        make_float2(v10, v11);
                }
            }
    }
}

// ---------------- InstanceNorm: 64 blocks = (graph, 16-ch quad) ----------------
__global__ void instnorm_kernel() {
    int g = blockIdx.x >> 2, cq = (blockIdx.x & 3) << 4;
    int t = threadIdx.x;          // 512
    int c = t & 15, r = t >> 4;   // r 0..31
    const float* basep = g_u + (size_t)g * NS * HID + cq + c;
    float* outp = g_h + (size_t)g * NS * HID + cq + c;
    __shared__ float red[32][16];
    float s = 0.f;
    for (int n = r; n < NS; n += 32) s += basep[(size_t)n * HID];
    red[r][c] = s;
    __syncthreads();
    if (r == 0) {
        float tot = 0.f;
        #pragma unroll
        for (int i = 0; i < 32; i++) tot += red[i][c];
        red[0][c] = tot * (1.0f / NS);
    }
    __syncthreads();
    float mean = red[0][c];
    __syncthreads();
    float s2 = 0.f;
    for (int n = r; n < NS; n += 32) {
        float d = basep[(size_t)n * HID] - mean;
        s2 = fmaf(d, d, s2);
    }
    red[r][c] = s2;
    __syncthreads();
    if (r == 0) {
        float tot = 0.f;
        #pragma unroll
        for (int i = 0; i < 32; i++) tot += red[i][c];
        red[0][c] = rsqrtf(tot * (1.0f / NS) + EPSF);
    }
    __syncthreads();
    float inv = red[0][c];
    for (int n = r; n < NS; n += 32)
        outp[(size_t)n * HID] = (basep[(size_t)n * HID] - mean) * inv;
}

// ---------------- decoder ----------------
__global__ void decoder_kernel(const float* __restrict__ W, const float* __restrict__ b,
                               float* __restrict__ out) {
    __shared__ float sW[HID * 3];
    __shared__ float sb[3];
    int t = threadIdx.x;
    if (t < HID * 3) sW[t] = W[t];
    if (t < 3) sb[t] = b[t];
    __syncthreads();
    int n = blockIdx.x * 256 + t;
    float a0 = sb[0], a1 = sb[1], a2 = sb[2];
    const float* hr = g_h + (size_t)n * HID;
    #pragma unroll 8
    for (int k = 0; k < HID; k++) {
        float v = hr[k];
        a0 = fmaf(v, sW[k * 3 + 0], a0);
        a1 = fmaf(v, sW[k * 3 + 1], a1);
        a2 = fmaf(v, sW[k * 3 + 2], a2);
    }
    float inv = rsqrtf(a0 * a0 + a1 * a1 + a2 * a2);
    a0 *= inv; a1 *= inv; a2 *= inv;
    g_X[n * 3 + 0] = a0; g_X[n * 3 + 1] = a1; g_X[n * 3 + 2] = a2;
    out[1 + n * 3 + 0] = a0; out[1 + n * 3 + 1] = a1; out[1 + n * 3 + 2] = a2;
}

// ---------------- MMD kernels ----------------
__global__ void kxx_kernel() {
    int bid = blockIdx.x;
    int g = bid >> 8, tm = (bid >> 4) & 15, tn = bid & 15;
    const float* Xg = g_X + (size_t)g * NS * 3;
    __shared__ float ax[128][4];
    __shared__ float ay[128][4];
    __shared__ float rs[256];
    int t = threadIdx.x;
    for (int i = t; i < 128 * 3; i += 256) {
        int row = i / 3, col = i - row * 3;
        ax[row][col] = Xg[tm * 128 * 3 + i];
        ay[row][col] = Xg[tn * 128 * 3 + i];
    }
    __syncthreads();
    int r0 = (t >> 4) << 3, cb = (t & 15) << 3;
    float yv[8][3];
    #pragma unroll
    for (int j = 0; j < 8; j++) {
        yv[j][0] = ay[cb + j][0]; yv[j][1] = ay[cb + j][1]; yv[j][2] = ay[cb + j][2];
    }
    float s = 0.f;
    #pragma unroll
    for (int i = 0; i < 8; i++) {
        float x0 = ax[r0 + i][0], x1 = ax[r0 + i][1], x2 = ax[r0 + i][2];
        #pragma unroll
        for (int j = 0; j < 8; j++) {
            float d = fmaf(x0, yv[j][0], fmaf(x1, yv[j][1], x2 * yv[j][2]));
            s += fexp(fmaf(2.f, d, -2.f));
        }
    }
    rs[t] = s;
    __syncthreads();
    for (int o = 128; o > 0; o >>= 1) { if (t < o) rs[t] += rs[t + o]; __syncthreads(); }
    if (t == 0) atomicAdd(&g_acc[g], rs[0]);
}

__global__ void kxy_kernel() {
    __shared__ float sy[64][4];
    __shared__ float rs[256];
    int t = threadIdx.x;
    int n = blockIdx.x * 256 + t;
    for (int i = t; i < 64 * 3; i += 256) { int row = i / 3; sy[row][i - row * 3] = g_Y[i]; }
    __syncthreads();
    float x0 = g_X[n * 3], x1 = g_X[n * 3 + 1], x2 = g_X[n * 3 + 2];
    float s = 0.f;
    #pragma unroll 8
    for (int j = 0; j < 64; j++) {
        float d = fmaf(x0, sy[j][0], fmaf(x1, sy[j][1], x2 * sy[j][2]));
        s += fexp(fmaf(2.f, d, -2.f));
    }
    rs[t] = s;
    __syncthreads();
    for (int o = 128; o > 0; o >>= 1) { if (t < o) rs[t] += rs[t + o]; __syncthreads(); }
    if (t == 0) atomicAdd(&g_acc[NBATCH + (n >> 11)], rs[0]);
}

__global__ void finalize_kernel(float* __restrict__ out) {
    __shared__ float rs[64];
    int t = threadIdx.x;
    float x0 = g_Y[t * 3], x1 = g_Y[t * 3 + 1], x2 = g_Y[t * 3 + 2];
    float s = 0.f;
    for (int j = 0; j < 64; j++) {
        float d = fmaf(x0, g_Y[j * 3], fmaf(x1, g_Y[j * 3 + 1], x2 * g_Y[j * 3 + 2]));
        s += fexp(fmaf(2.f, d, -2.f));
    }
    rs[t] = s;
    __syncthreads();
    if (t == 0) {
        float kyy = 0.f;
        for (int j = 0; j < 64; j++) kyy += rs[j];
        kyy *= (1.0f / (64.f * 64.f));
        float loss = 0.f;
        for (int b = 0; b < NBATCH; b++) {
            float kxx = g_acc[b] * (1.0f / ((float)NS * (float)NS));
            float kxy = g_acc[NBATCH + b] * (1.0f / ((float)NS * 64.f));
            loss += kxx - 2.f * kxy + kyy;
        }
        out[0] = loss * (1.0f / NBATCH);
    }
}

// ---------------- launch ----------------
extern "C" void kernel_launch(void* const* d_in, const int* in_sizes, int n_in,
                              void* d_out, int out_size) {
    const float* x    = (const float*)d_in[0];
    const int*   esrc = (const int*)d_in[1];
    const int*   edst = (const int*)d_in[2];
    const float* encW = (const float*)d_in[4];
    const float* encb = (const float*)d_in[5];
    const float* m1W  = (const float*)d_in[6];
    const float* m1b  = (const float*)d_in[7];
    const float* m2W  = (const float*)d_in[8];
    const float* m2b  = (const float*)d_in[9];
    const float* u1W  = (const float*)d_in[10];
    const float* u1b  = (const float*)d_in[11];
    const float* u2W  = (const float*)d_in[12];
    const float* u2b  = (const float*)d_in[13];
    const float* decW = (const float*)d_in[14];
    const float* decb = (const float*)d_in[15];
    float* out = (float*)d_out;

    cudaFuncSetAttribute((const void*)mlp_mma_kernel<true>,
                         cudaFuncAttributeMaxDynamicSharedMemorySize, SMEM_MMA_BYTES);
    cudaFuncSetAttribute((const void*)mlp_mma_kernel<false>,
                         cudaFuncAttributeMaxDynamicSharedMemorySize, SMEM_MMA_BYTES);

    compute_Y_kernel<<<1, 64>>>();
    encoder_kernel<<<NNODES * HID / 256, 256>>>(x, encW, encb);

    for (int l = 0; l < 4; l++) {
        zero_agg_kernel<<<NNODES * HID / 1024, 256>>>();
        mlp_mma_kernel<true><<<148, 256, SMEM_MMA_BYTES>>>(
            m1W + (size_t)l * 128 * 64, m1b + (size_t)l * 64,
            m2W + (size_t)l * 64 * 64,  m2b + (size_t)l * 64, esrc, edst);
        mlp_mma_kernel<false><<<128, 256, SMEM_MMA_BYTES>>>(
            u1W + (size_t)l * 128 * 64, u1b + (size_t)l * 64,
            u2W + (size_t)l * 64 * 64,  u2b + (size_t)l * 64, nullptr, nullptr);
        instnorm_kernel<<<64, 512>>>();
    }

    zero_acc_kernel<<<1, 32>>>();
    decoder_kernel<<<NNODES / 256, 256>>>(decW, decb, out);
    kxy_kernel<<<NNODES / 256, 256>>>();
    kxx_kernel<<<NBATCH * 16 * 16, 256>>>();
    finalize_kernel<<<1, 64>>>(out);
}

// round 7
// speedup vs baseline: 2.6091x; 1.1632x over previous
#include <cuda_runtime.h>
#include <cuda_bf16.h>
#include <math.h>
#include <stdint.h>

#define NNODES 32768
#define NBATCH 16
#define NS 2048
#define HID 64
#define ETOT 524288
#define TM 64
#define EPSF 1e-5f

// ---------------- scratch ----------------
__device__ float g_h[NNODES * HID];
__device__ float g_agg[NNODES * HID];
__device__ float g_u[NNODES * HID];
__device__ float g_X[NNODES * 3];
__device__ float g_Y[64 * 3];
__device__ float g_acc[2 * NBATCH];

// ---------------- smem layout (bytes). Rows padded +16B for conflict-free ldmatrix ----
// A [64][136] bf16 (272B/row) ; B1 = W1^T [64][136] ; Mid [64][72] (144B) ; B2 = W2^T [64][72]
#define A_HI   0
#define A_LO   17408
#define B1_HI  34816
#define B1_LO  52224
#define MID_HI 69632
#define MID_LO 78848
#define B2_HI  88064
#define B2_LO  97280
#define BIAS1  106496
#define BIAS2  106752
#define DSTO   107008
#define SRCO   107264
#define SMEM_MMA_BYTES 107520

static __device__ __forceinline__ uint32_t cvta_smem(const void* p) {
    uint32_t a;
    asm("{ .reg .u64 t; cvta.to.shared.u64 t, %1; cvt.u32.u64 %0, t; }" : "=r"(a) : "l"(p));
    return a;
}
static __device__ __forceinline__ void ldsm4(uint32_t* r, uint32_t addr) {
    asm volatile("ldmatrix.sync.aligned.m8n8.x4.shared.b16 {%0,%1,%2,%3}, [%4];"
                 : "=r"(r[0]), "=r"(r[1]), "=r"(r[2]), "=r"(r[3]) : "r"(addr));
}
static __device__ __forceinline__ void mma_bf16(float* c, const uint32_t* a, const uint32_t* b) {
    asm volatile(
        "mma.sync.aligned.m16n8k16.row.col.f32.bf16.bf16.f32 "
        "{%0,%1,%2,%3}, {%4,%5,%6,%7}, {%8,%9}, {%0,%1,%2,%3};"
        : "+f"(c[0]), "+f"(c[1]), "+f"(c[2]), "+f"(c[3])
        : "r"(a[0]), "r"(a[1]), "r"(a[2]), "r"(a[3]), "r"(b[0]), "r"(b[1]));
}

// split 8 floats into bf16 hi/lo packed words
static __device__ __forceinline__ void split8(const float* f, uint4& hi, uint4& lo) {
    uint32_t hw[4], lw[4];
    #pragma unroll
    for (int j = 0; j < 4; j++) {
        __nv_bfloat16 h0 = __float2bfloat16(f[2 * j]);
        __nv_bfloat16 h1 = __float2bfloat16(f[2 * j + 1]);
        float r0 = f[2 * j] - __bfloat162float(h0);
        float r1 = f[2 * j + 1] - __bfloat162float(h1);
        __nv_bfloat16 l0 = __float2bfloat16(r0);
        __nv_bfloat16 l1 = __float2bfloat16(r1);
        hw[j] = ((uint32_t)__bfloat16_as_ushort(h1) << 16) | (uint32_t)__bfloat16_as_ushort(h0);
        lw[j] = ((uint32_t)__bfloat16_as_ushort(l1) << 16) | (uint32_t)__bfloat16_as_ushort(l0);
    }
    hi = make_uint4(hw[0], hw[1], hw[2], hw[3]);
    lo = make_uint4(lw[0], lw[1], lw[2], lw[3]);
}
static __device__ __forceinline__ void split2(float x, float y, uint32_t& hi, uint32_t& lo) {
    __nv_bfloat16 hx = __float2bfloat16(x), hy = __float2bfloat16(y);
    __nv_bfloat16 lx = __float2bfloat16(x - __bfloat162float(hx));
    __nv_bfloat16 ly = __float2bfloat16(y - __bfloat162float(hy));
    hi = ((uint32_t)__bfloat16_as_ushort(hy) << 16) | (uint32_t)__bfloat16_as_ushort(hx);
    lo = ((uint32_t)__bfloat16_as_ushort(ly) << 16) | (uint32_t)__bfloat16_as_ushort(lx);
}

// fast exp, FFMA-only
__device__ __forceinline__ float fexp(float x) {
    const float L2E = 1.4426950408889634f;
    float t = fmaf(x, L2E, 12582912.0f);
    float kf = t - 12582912.0f;
    float f = fmaf(x, L2E, -kf);
    float p = 1.33335581e-3f;
    p = fmaf(p, f, 9.61812911e-3f);
    p = fmaf(p, f, 5.55041087e-2f);
    p = fmaf(p, f, 2.40226507e-1f);
    p = fmaf(p, f, 6.93147181e-1f);
    p = fmaf(p, f, 1.0f);
    int ik = (int)kf;
    return __int_as_float(__float_as_int(p) + (ik << 23));
}

__global__ void compute_Y_kernel() {
    int i = threadIdx.x;
    if (i < 64) {
        double phi = 3.14159265358979323846 * (3.0 - sqrt(5.0));
        double y = 1.0 - 2.0 * (double)i / 63.0;
        double r = sqrt(fmax(0.0, 1.0 - y * y));
        double th = phi * (double)i;
        g_Y[i * 3 + 0] = (float)(cos(th) * r);
        g_Y[i * 3 + 1] = (float)y;
        g_Y[i * 3 + 2] = (float)(sin(th) * r);
    }
}

__global__ void zero_agg_kernel() {
    int i = blockIdx.x * blockDim.x + threadIdx.x;
    reinterpret_cast<float4*>(g_agg)[i] = make_float4(0.f, 0.f, 0.f, 0.f);
}

__global__ void zero_acc_kernel() {
    int i = threadIdx.x;
    if (i < 2 * NBATCH) g_acc[i] = 0.f;
}

__global__ void encoder_kernel(const float* __restrict__ x,
                               const float* __restrict__ W,
                               const float* __restrict__ b) {
    __shared__ float sW[3 * HID];
    __shared__ float sb[HID];
    int t = threadIdx.x;
    if (t < 3 * HID) sW[t] = W[t];
    if (t < HID) sb[t] = b[t];
    __syncthreads();
    int idx = blockIdx.x * 256 + t;
    int n = idx >> 6, c = idx & 63;
    float x0 = x[n * 3 + 0], x1 = x[n * 3 + 1], x2 = x[n * 3 + 2];
    g_h[idx] = fmaf(x0, sW[c], fmaf(x1, sW[HID + c], fmaf(x2, sW[2 * HID + c], sb[c])));
}

// ============ warp-MMA fused 2-layer MLP, TM=64, 2 CTAs/SM ============
template <bool EDGE>
__global__ void __launch_bounds__(256, 2) mlp_mma_kernel(
    const float* __restrict__ W1g, const float* __restrict__ b1g,
    const float* __restrict__ W2g, const float* __restrict__ b2g,
    const int* __restrict__ esrc, const int* __restrict__ edst) {
    extern __shared__ char sp[];
    const uint32_t sb = cvta_smem(sp);
    const int t = threadIdx.x, lane = t & 31, wid = t >> 5;

    float* b1v = reinterpret_cast<float*>(sp + BIAS1);
    float* b2v = reinterpret_cast<float*>(sp + BIAS2);
    int* dstA = reinterpret_cast<int*>(sp + DSTO);
    int* srcA = reinterpret_cast<int*>(sp + SRCO);

    // ---- weights: B1 = W1^T [64 n][136 k pad] bf16 hi/lo ; B2 = W2^T [64][72] ----
    for (int i = t; i < 128 * 64; i += 256) {
        int k = i >> 6, n = i & 63;
        float w = W1g[i];
        __nv_bfloat16 hi = __float2bfloat16(w);
        __nv_bfloat16 lo = __float2bfloat16(w - __bfloat162float(hi));
        reinterpret_cast<__nv_bfloat16*>(sp + B1_HI)[n * 136 + k] = hi;
        reinterpret_cast<__nv_bfloat16*>(sp + B1_LO)[n * 136 + k] = lo;
    }
    for (int i = t; i < 64 * 64; i += 256) {
        int k = i >> 6, n = i & 63;
        float w = W2g[i];
        __nv_bfloat16 hi = __float2bfloat16(w);
        __nv_bfloat16 lo = __float2bfloat16(w - __bfloat162float(hi));
        reinterpret_cast<__nv_bfloat16*>(sp + B2_HI)[n * 72 + k] = hi;
        reinterpret_cast<__nv_bfloat16*>(sp + B2_LO)[n * 72 + k] = lo;
    }
    if (t < 64) { b1v[t] = b1g[t]; b2v[t] = b2g[t]; }

    // per-thread fragment geometry (warp = 16 rows x 32 cols)
    const int g = lane >> 3;
    const int a_row = (g & 1) * 8 + (lane & 7);
    const int a_koff = (g >> 1) * 8;
    const int b_row = (g >> 1) * 8 + (lane & 7);
    const int b_koff = (g & 1) * 8;
    const int m0 = (wid & 3) * 16;
    const int n0 = (wid >> 2) * 32;
    const int er = lane >> 2, ec = lane & 3;

    const uint32_t aA = sb + A_HI + (uint32_t)(m0 + a_row) * 272 + a_koff * 2;
    const uint32_t aM = sb + MID_HI + (uint32_t)(m0 + a_row) * 144 + a_koff * 2;
    uint32_t aB[2], aB2[2];
    #pragma unroll
    for (int i = 0; i < 2; i++) {
        aB[i]  = sb + B1_HI + (uint32_t)(n0 + 16 * i + b_row) * 272 + b_koff * 2;
        aB2[i] = sb + B2_HI + (uint32_t)(n0 + 16 * i + b_row) * 144 + b_koff * 2;
    }

    const int ntiles = (EDGE ? ETOT : NNODES) / TM;
    for (int tile = blockIdx.x; tile < ntiles; tile += gridDim.x) {
        const int base = tile * TM;
        __syncthreads();                                  // prev tile fully done
        if (EDGE) {
            if (t < TM) dstA[t] = edst[base + t];
            else if (t < 2 * TM) srcA[t - TM] = esrc[base + t - TM];
            __syncthreads();
        }
        // ---- gather + split into A (k 0-63 = dst/h, 64-127 = src/agg) ----
        #pragma unroll
        for (int i = t; i < 1024; i += 256) {
            int half = i >> 9, rem = i & 511;
            int e = rem >> 3, c = rem & 7;
            const float* gs;
            int node;
            if (EDGE) { node = half ? srcA[e] : dstA[e]; gs = g_h; }
            else      { node = base + e; gs = half ? g_agg : g_h; }
            const float4* p4 = reinterpret_cast<const float4*>(gs + (size_t)node * HID + c * 8);
            float4 va = p4[0], vb = p4[1];
            float f[8] = {va.x, va.y, va.z, va.w, vb.x, vb.y, vb.z, vb.w};
            uint4 hi, lo;
            split8(f, hi, lo);
            uint32_t off = (uint32_t)e * 272 + half * 128 + c * 16;
            *reinterpret_cast<uint4*>(sp + A_HI + off) = hi;
            *reinterpret_cast<uint4*>(sp + A_LO + off) = lo;
        }
        __syncthreads();
        // ---- GEMM1: [64,64] = A[64,128] @ B1^T, 3-term bf16 split ----
        float acc[4][4];
        #pragma unroll
        for (int nt = 0; nt < 4; nt++)
            #pragma unroll
            for (int j = 0; j < 4; j++) acc[nt][j] = 0.f;
        #pragma unroll
        for (int kk = 0; kk < 8; kk++) {
            uint32_t ah[4], al[4], bh[2][4], bl[2][4];
            ldsm4(ah, aA + kk * 32);
            ldsm4(al, aA + 17408 + kk * 32);
            #pragma unroll
            for (int i = 0; i < 2; i++) {
                ldsm4(bh[i], aB[i] + kk * 32);
                ldsm4(bl[i], aB[i] + 17408 + kk * 32);
            }
            #pragma unroll
            for (int nt = 0; nt < 4; nt++) {
                const uint32_t* bhp = &bh[nt >> 1][(nt & 1) * 2];
                const uint32_t* blp = &bl[nt >> 1][(nt & 1) * 2];
                mma_bf16(acc[nt], ah, bhp);
                mma_bf16(acc[nt], al, bhp);
                mma_bf16(acc[nt], ah, blp);
            }
        }
        // ---- epilogue 1: bias+relu, split -> Mid ----
        #pragma unroll
        for (int nt = 0; nt < 4; nt++) {
            int r0 = m0 + er, r1 = r0 + 8;
            int n = n0 + 8 * nt + 2 * ec;
            float v00 = fmaxf(acc[nt][0] + b1v[n], 0.f);
            float v01 = fmaxf(acc[nt][1] + b1v[n + 1], 0.f);
            float v10 = fmaxf(acc[nt][2] + b1v[n], 0.f);
            float v11 = fmaxf(acc[nt][3] + b1v[n + 1], 0.f);
            uint32_t h0, l0, h1, l1;
            split2(v00, v01, h0, l0);
            split2(v10, v11, h1, l1);
            int w0 = r0 * 36 + (n >> 1), w1 = r1 * 36 + (n >> 1);
            reinterpret_cast<uint32_t*>(sp + MID_HI)[w0] = h0;
            reinterpret_cast<uint32_t*>(sp + MID_LO)[w0] = l0;
            reinterpret_cast<uint32_t*>(sp + MID_HI)[w1] = h1;
            reinterpret_cast<uint32_t*>(sp + MID_LO)[w1] = l1;
        }
        __syncthreads();
        // ---- GEMM2: [64,64] = Mid[64,64] @ B2^T ----
        float acc2[4][4];
        #pragma unroll
        for (int nt = 0; nt < 4; nt++)
            #pragma unroll
            for (int j = 0; j < 4; j++) acc2[nt][j] = 0.f;
        #pragma unroll
        for (int kk = 0; kk < 4; kk++) {
            uint32_t ah[4], al[4], bh[2][4], bl[2][4];
            ldsm4(ah, aM + kk * 32);
            ldsm4(al, aM + 9216 + kk * 32);
            #pragma unroll
            for (int i = 0; i < 2; i++) {
                ldsm4(bh[i], aB2[i] + kk * 32);
                ldsm4(bl[i], aB2[i] + 9216 + kk * 32);
            }
            #pragma unroll
            for (int nt = 0; nt < 4; nt++) {
                const uint32_t* bhp = &bh[nt >> 1][(nt & 1) * 2];
                const uint32_t* blp = &bl[nt >> 1][(nt & 1) * 2];
                mma_bf16(acc2[nt], ah, bhp);
                mma_bf16(acc2[nt], al, bhp);
                mma_bf16(acc2[nt], ah, blp);
            }
        }
        // ---- epilogue 2: bias+relu -> scatter/store ----
        #pragma unroll
        for (int nt = 0; nt < 4; nt++) {
            int r0 = m0 + er, r1 = r0 + 8;
            int n = n0 + 8 * nt + 2 * ec;
            float v00 = fmaxf(acc2[nt][0] + b2v[n], 0.f);
            float v01 = fmaxf(acc2[nt][1] + b2v[n + 1], 0.f);
            float v10 = fmaxf(acc2[nt][2] + b2v[n], 0.f);
            float v11 = fmaxf(acc2[nt][3] + b2v[n + 1], 0.f);
            if (EDGE) {
                float* p0 = g_agg + (size_t)dstA[r0] * HID + n;
                float* p1 = g_agg + (size_t)dstA[r1] * HID + n;
                asm volatile("red.global.add.v2.f32 [%0], {%1,%2};"
                             :: "l"(p0), "f"(v00), "f"(v01) : "memory");
                asm volatile("red.global.add.v2.f32 [%0], {%1,%2};"
                             :: "l"(p1), "f"(v10), "f"(v11) : "memory");
            } else {
                *reinterpret_cast<float2*>(g_u + (size_t)(base + r0) * HID + n) =
                    make_float2(v00, v01);
                *reinterpret_cast<float2*>(g_u + (size_t)(base + r1) * HID + n) =
                    make_float2(v10, v11);
            }
        }
    }
}

// ---------------- InstanceNorm: 64 blocks = (graph, 16-ch quad) ----------------
__global__ void instnorm_kernel() {
    int g = blockIdx.x >> 2, cq = (blockIdx.x & 3) << 4;
    int t = threadIdx.x;          // 512
    int c = t & 15, r = t >> 4;   // r 0..31
    const float* basep = g_u + (size_t)g * NS * HID + cq + c;
    float* outp = g_h + (size_t)g * NS * HID + cq + c;
    __shared__ float red[32][16];
    float s = 0.f;
    for (int n = r; n < NS; n += 32) s += basep[(size_t)n * HID];
    red[r][c] = s;
    __syncthreads();
    if (r == 0) {
        float tot = 0.f;
        #pragma unroll
        for (int i = 0; i < 32; i++) tot += red[i][c];
        red[0][c] = tot * (1.0f / NS);
    }
    __syncthreads();
    float mean = red[0][c];
    __syncthreads();
    float s2 = 0.f;
    for (int n = r; n < NS; n += 32) {
        float d = basep[(size_t)n * HID] - mean;
        s2 = fmaf(d, d, s2);
    }
    red[r][c] = s2;
    __syncthreads();
    if (r == 0) {
        float tot = 0.f;
        #pragma unroll
        for (int i = 0; i < 32; i++) tot += red[i][c];
        red[0][c] = rsqrtf(tot * (1.0f / NS) + EPSF);
    }
    __syncthreads();
    float inv = red[0][c];
    for (int n = r; n < NS; n += 32)
        outp[(size_t)n * HID] = (basep[(size_t)n * HID] - mean) * inv;
}

// ---------------- decoder ----------------
__global__ void decoder_kernel(const float* __restrict__ W, const float* __restrict__ b,
                               float* __restrict__ out) {
    __shared__ float sW[HID * 3];
    __shared__ float sb[3];
    int t = threadIdx.x;
    if (t < HID * 3) sW[t] = W[t];
    if (t < 3) sb[t] = b[t];
    __syncthreads();
    int n = blockIdx.x * 256 + t;
    float a0 = sb[0], a1 = sb[1], a2 = sb[2];
    const float* hr = g_h + (size_t)n * HID;
    #pragma unroll 8
    for (int k = 0; k < HID; k++) {
        float v = hr[k];
        a0 = fmaf(v, sW[k * 3 + 0], a0);
        a1 = fmaf(v, sW[k * 3 + 1], a1);
        a2 = fmaf(v, sW[k * 3 + 2], a2);
    }
    float inv = rsqrtf(a0 * a0 + a1 * a1 + a2 * a2);
    a0 *= inv; a1 *= inv; a2 *= inv;
    g_X[n * 3 + 0] = a0; g_X[n * 3 + 1] = a1; g_X[n * 3 + 2] = a2;
    out[1 + n * 3 + 0] = a0; out[1 + n * 3 + 1] = a1; out[1 + n * 3 + 2] = a2;
}

// ---------------- MMD kernels ----------------
__global__ void kxx_kernel() {
    int bid = blockIdx.x;
    int g = bid >> 8, tm = (bid >> 4) & 15, tn = bid & 15;
    const float* Xg = g_X + (size_t)g * NS * 3;
    __shared__ float ax[128][4];
    __shared__ float ay[128][4];
    __shared__ float rs[256];
    int t = threadIdx.x;
    for (int i = t; i < 128 * 3; i += 256) {
        int row = i / 3, col = i - row * 3;
        ax[row][col] = Xg[tm * 128 * 3 + i];
        ay[row][col] = Xg[tn * 128 * 3 + i];
    }
    __syncthreads();
    int r0 = (t >> 4) << 3, cb = (t & 15) << 3;
    float yv[8][3];
    #pragma unroll
    for (int j = 0; j < 8; j++) {
        yv[j][0] = ay[cb + j][0]; yv[j][1] = ay[cb + j][1]; yv[j][2] = ay[cb + j][2];
    }
    float s = 0.f;
    #pragma unroll
    for (int i = 0; i < 8; i++) {
        float x0 = ax[r0 + i][0], x1 = ax[r0 + i][1], x2 = ax[r0 + i][2];
        #pragma unroll
        for (int j = 0; j < 8; j++) {
            float d = fmaf(x0, yv[j][0], fmaf(x1, yv[j][1], x2 * yv[j][2]));
            s += fexp(fmaf(2.f, d, -2.f));
        }
    }
    rs[t] = s;
    __syncthreads();
    for (int o = 128; o > 0; o >>= 1) { if (t < o) rs[t] += rs[t + o]; __syncthreads(); }
    if (t == 0) atomicAdd(&g_acc[g], rs[0]);
}

__global__ void kxy_kernel() {
    __shared__ float sy[64][4];
    __shared__ float rs[256];
    int t = threadIdx.x;
    int n = blockIdx.x * 256 + t;
    for (int i = t; i < 64 * 3; i += 256) { int row = i / 3; sy[row][i - row * 3] = g_Y[i]; }
    __syncthreads();
    float x0 = g_X[n * 3], x1 = g_X[n * 3 + 1], x2 = g_X[n * 3 + 2];
    float s = 0.f;
    #pragma unroll 8
    for (int j = 0; j < 64; j++) {
        float d = fmaf(x0, sy[j][0], fmaf(x1, sy[j][1], x2 * sy[j][2]));
        s += fexp(fmaf(2.f, d, -2.f));
    }
    rs[t] = s;
    __syncthreads();
    for (int o = 128; o > 0; o >>= 1) { if (t < o) rs[t] += rs[t + o]; __syncthreads(); }
    if (t == 0) atomicAdd(&g_acc[NBATCH + (n >> 11)], rs[0]);
}

__global__ void finalize_kernel(float* __restrict__ out) {
    __shared__ float rs[64];
    int t = threadIdx.x;
    float x0 = g_Y[t * 3], x1 = g_Y[t * 3 + 1], x2 = g_Y[t * 3 + 2];
    float s = 0.f;
    for (int j = 0; j < 64; j++) {
        float d = fmaf(x0, g_Y[j * 3], fmaf(x1, g_Y[j * 3 + 1], x2 * g_Y[j * 3 + 2]));
        s += fexp(fmaf(2.f, d, -2.f));
    }
    rs[t] = s;
    __syncthreads();
    if (t == 0) {
        float kyy = 0.f;
        for (int j = 0; j < 64; j++) kyy += rs[j];
        kyy *= (1.0f / (64.f * 64.f));
        float loss = 0.f;
        for (int b = 0; b < NBATCH; b++) {
            float kxx = g_acc[b] * (1.0f / ((float)NS * (float)NS));
            float kxy = g_acc[NBATCH + b] * (1.0f / ((float)NS * 64.f));
            loss += kxx - 2.f * kxy + kyy;
        }
        out[0] = loss * (1.0f / NBATCH);
    }
}

// ---------------- launch ----------------
extern "C" void kernel_launch(void* const* d_in, const int* in_sizes, int n_in,
                              void* d_out, int out_size) {
    const float* x    = (const float*)d_in[0];
    const int*   esrc = (const int*)d_in[1];
    const int*   edst = (const int*)d_in[2];
    const float* encW = (const float*)d_in[4];
    const float* encb = (const float*)d_in[5];
    const float* m1W  = (const float*)d_in[6];
    const float* m1b  = (const float*)d_in[7];
    const float* m2W  = (const float*)d_in[8];
    const float* m2b  = (const float*)d_in[9];
    const float* u1W  = (const float*)d_in[10];
    const float* u1b  = (const float*)d_in[11];
    const float* u2W  = (const float*)d_in[12];
    const float* u2b  = (const float*)d_in[13];
    const float* decW = (const float*)d_in[14];
    const float* decb = (const float*)d_in[15];
    float* out = (float*)d_out;

    cudaFuncSetAttribute((const void*)mlp_mma_kernel<true>,
                         cudaFuncAttributeMaxDynamicSharedMemorySize, SMEM_MMA_BYTES);
    cudaFuncSetAttribute((const void*)mlp_mma_kernel<false>,
                         cudaFuncAttributeMaxDynamicSharedMemorySize, SMEM_MMA_BYTES);

    compute_Y_kernel<<<1, 64>>>();
    encoder_kernel<<<NNODES * HID / 256, 256>>>(x, encW, encb);

    for (int l = 0; l < 4; l++) {
        zero_agg_kernel<<<NNODES * HID / 1024, 256>>>();
        mlp_mma_kernel<true><<<296, 256, SMEM_MMA_BYTES>>>(
            m1W + (size_t)l * 128 * 64, m1b + (size_t)l * 64,
            m2W + (size_t)l * 64 * 64,  m2b + (size_t)l * 64, esrc, edst);
        mlp_mma_kernel<false><<<296, 256, SMEM_MMA_BYTES>>>(
            u1W + (size_t)l * 128 * 64, u1b + (size_t)l * 64,
            u2W + (size_t)l * 64 * 64,  u2b + (size_t)l * 64, nullptr, nullptr);
        instnorm_kernel<<<64, 512>>>();
    }

    zero_acc_kernel<<<1, 32>>>();
    decoder_kernel<<<NNODES / 256, 256>>>(decW, decb, out);
    kxy_kernel<<<NNODES / 256, 256>>>();
    kxx_kernel<<<NBATCH * 16 * 16, 256>>>();
    finalize_kernel<<<1, 64>>>(out);
}

// round 8
// speedup vs baseline: 3.5962x; 1.3783x over previous
#include <cuda_runtime.h>
#include <cuda_bf16.h>
#include <math.h>
#include <stdint.h>

#define NNODES 32768
#define NBATCH 16
#define NS 2048
#define HID 64
#define ETOT 524288
#define TM 128
#define EPSF 1e-5f

// ---------------- scratch ----------------
__device__ float g_h[NNODES * HID];
__device__ float g_agg[NNODES * HID];
__device__ float g_u[NNODES * HID];
__device__ float g_X[NNODES * 3];
__device__ float g_Y[64 * 3];
__device__ float g_acc[2 * NBATCH];

// ---------------- smem: weights only (tile-invariant) ----------------
// B1 = W1^T [64 n][136 k pad] bf16 (272B/row); B2 = W2^T [64][72] (144B/row)
#define B1_HI  0
#define B1_LO  17408
#define B2_HI  34816
#define B2_LO  44032
#define BIAS1  53248
#define BIAS2  53504
#define SMEM_MMA_BYTES 53760

static __device__ __forceinline__ uint32_t cvta_smem(const void* p) {
    uint32_t a;
    asm("{ .reg .u64 t; cvta.to.shared.u64 t, %1; cvt.u32.u64 %0, t; }" : "=r"(a) : "l"(p));
    return a;
}
static __device__ __forceinline__ void ldsm4(uint32_t* r, uint32_t addr) {
    asm volatile("ldmatrix.sync.aligned.m8n8.x4.shared.b16 {%0,%1,%2,%3}, [%4];"
                 : "=r"(r[0]), "=r"(r[1]), "=r"(r[2]), "=r"(r[3]) : "r"(addr));
}
static __device__ __forceinline__ void mma_bf16(float* c, const uint32_t* a, const uint32_t* b) {
    asm volatile(
        "mma.sync.aligned.m16n8k16.row.col.f32.bf16.bf16.f32 "
        "{%0,%1,%2,%3}, {%4,%5,%6,%7}, {%8,%9}, {%0,%1,%2,%3};"
        : "+f"(c[0]), "+f"(c[1]), "+f"(c[2]), "+f"(c[3])
        : "r"(a[0]), "r"(a[1]), "r"(a[2]), "r"(a[3]), "r"(b[0]), "r"(b[1]));
}
// pack two floats into bf16x2 hi + lo correction words
static __device__ __forceinline__ void split2(float x, float y, uint32_t& hi, uint32_t& lo) {
    __nv_bfloat16 hx = __float2bfloat16(x), hy = __float2bfloat16(y);
    __nv_bfloat16 lx = __float2bfloat16(x - __bfloat162float(hx));
    __nv_bfloat16 ly = __float2bfloat16(y - __bfloat162float(hy));
    hi = ((uint32_t)__bfloat16_as_ushort(hy) << 16) | (uint32_t)__bfloat16_as_ushort(hx);
    lo = ((uint32_t)__bfloat16_as_ushort(ly) << 16) | (uint32_t)__bfloat16_as_ushort(lx);
}

// fast exp, FFMA-only
__device__ __forceinline__ float fexp(float x) {
    const float L2E = 1.4426950408889634f;
    float t = fmaf(x, L2E, 12582912.0f);
    float kf = t - 12582912.0f;
    float f = fmaf(x, L2E, -kf);
    float p = 1.33335581e-3f;
    p = fmaf(p, f, 9.61812911e-3f);
    p = fmaf(p, f, 5.55041087e-2f);
    p = fmaf(p, f, 2.40226507e-1f);
    p = fmaf(p, f, 6.93147181e-1f);
    p = fmaf(p, f, 1.0f);
    int ik = (int)kf;
    return __int_as_float(__float_as_int(p) + (ik << 23));
}

__global__ void compute_Y_kernel() {
    int i = threadIdx.x;
    if (i < 64) {
        double phi = 3.14159265358979323846 * (3.0 - sqrt(5.0));
        double y = 1.0 - 2.0 * (double)i / 63.0;
        double r = sqrt(fmax(0.0, 1.0 - y * y));
        double th = phi * (double)i;
        g_Y[i * 3 + 0] = (float)(cos(th) * r);
        g_Y[i * 3 + 1] = (float)y;
        g_Y[i * 3 + 2] = (float)(sin(th) * r);
    }
}

__global__ void zero_agg_kernel() {
    int i = blockIdx.x * blockDim.x + threadIdx.x;
    reinterpret_cast<float4*>(g_agg)[i] = make_float4(0.f, 0.f, 0.f, 0.f);
}

__global__ void zero_acc_kernel() {
    int i = threadIdx.x;
    if (i < 2 * NBATCH) g_acc[i] = 0.f;
}

__global__ void encoder_kernel(const float* __restrict__ x,
                               const float* __restrict__ W,
                               const float* __restrict__ b) {
    __shared__ float sW[3 * HID];
    __shared__ float sb[HID];
    int t = threadIdx.x;
    if (t < 3 * HID) sW[t] = W[t];
    if (t < HID) sb[t] = b[t];
    __syncthreads();
    int idx = blockIdx.x * 256 + t;
    int n = idx >> 6, c = idx & 63;
    float x0 = x[n * 3 + 0], x1 = x[n * 3 + 1], x2 = x[n * 3 + 2];
    g_h[idx] = fmaf(x0, sW[c], fmaf(x1, sW[HID + c], fmaf(x2, sW[2 * HID + c], sb[c])));
}

// ============ register-resident back-to-back warp-MMA MLP ============
// TM=128 rows/tile, 8 warps, warp = m16 x n64. No per-tile __syncthreads.
template <bool EDGE>
__global__ void __launch_bounds__(256, 2) mlp_mma_kernel(
    const float* __restrict__ W1g, const float* __restrict__ b1g,
    const float* __restrict__ W2g, const float* __restrict__ b2g,
    const int* __restrict__ esrc, const int* __restrict__ edst) {
    extern __shared__ char sp[];
    const uint32_t sb = cvta_smem(sp);
    const int t = threadIdx.x, lane = t & 31, wid = t >> 5;

    float* b1v = reinterpret_cast<float*>(sp + BIAS1);
    float* b2v = reinterpret_cast<float*>(sp + BIAS2);

    // ---- load tile-invariant weights (once) ----
    for (int i = t; i < 128 * 64; i += 256) {
        int k = i >> 6, n = i & 63;
        float w = W1g[i];
        __nv_bfloat16 hi = __float2bfloat16(w);
        __nv_bfloat16 lo = __float2bfloat16(w - __bfloat162float(hi));
        reinterpret_cast<__nv_bfloat16*>(sp + B1_HI)[n * 136 + k] = hi;
        reinterpret_cast<__nv_bfloat16*>(sp + B1_LO)[n * 136 + k] = lo;
    }
    for (int i = t; i < 64 * 64; i += 256) {
        int k = i >> 6, n = i & 63;
        float w = W2g[i];
        __nv_bfloat16 hi = __float2bfloat16(w);
        __nv_bfloat16 lo = __float2bfloat16(w - __bfloat162float(hi));
        reinterpret_cast<__nv_bfloat16*>(sp + B2_HI)[n * 72 + k] = hi;
        reinterpret_cast<__nv_bfloat16*>(sp + B2_LO)[n * 72 + k] = lo;
    }
    if (t < 64) { b1v[t] = b1g[t]; b2v[t] = b2g[t]; }
    __syncthreads();      // the ONLY barrier

    const int g = lane >> 3;
    const int b_row = (g >> 1) * 8 + (lane & 7);
    const int b_koff = (g & 1) * 8;
    const int er = lane >> 2, ec = lane & 3;
    const int m0 = wid * 16;

    // B ldsm base addresses (n-slab stride added in-loop)
    const uint32_t aB1 = sb + B1_HI + (uint32_t)b_row * 272 + b_koff * 2;
    const uint32_t aB2 = sb + B2_HI + (uint32_t)b_row * 144 + b_koff * 2;

    const int ntiles = (EDGE ? ETOT : NNODES) / TM;
    for (int tile = blockIdx.x; tile < ntiles; tile += gridDim.x) {
        const int base = tile * TM;
        const int r0 = base + m0 + er, r1 = r0 + 8;
        const float *rowD0, *rowD1, *rowS0, *rowS1;
        int d0, d1;
        if (EDGE) {
            d0 = edst[r0]; d1 = edst[r1];
            int s0 = esrc[r0], s1 = esrc[r1];
            rowD0 = g_h + (size_t)d0 * HID;  rowD1 = g_h + (size_t)d1 * HID;
            rowS0 = g_h + (size_t)s0 * HID;  rowS1 = g_h + (size_t)s1 * HID;
        } else {
            rowD0 = g_h + (size_t)r0 * HID;   rowD1 = g_h + (size_t)r1 * HID;
            rowS0 = g_agg + (size_t)r0 * HID; rowS1 = g_agg + (size_t)r1 * HID;
        }

        // ---- GEMM1: acc1[m16 x n64] = A[m16 x k128] @ B1^T, 3-term split ----
        float acc1[8][4];
        #pragma unroll
        for (int nt = 0; nt < 8; nt++)
            #pragma unroll
            for (int j = 0; j < 4; j++) acc1[nt][j] = 0.f;
        #pragma unroll
        for (int kk = 0; kk < 8; kk++) {
            const float* q0 = (kk < 4) ? rowD0 : rowS0;
            const float* q1 = (kk < 4) ? rowD1 : rowS1;
            int kb = (kk & 3) * 16;
            float2 p00 = *reinterpret_cast<const float2*>(q0 + kb + 2 * ec);
            float2 p10 = *reinterpret_cast<const float2*>(q1 + kb + 2 * ec);
            float2 p01 = *reinterpret_cast<const float2*>(q0 + kb + 8 + 2 * ec);
            float2 p11 = *reinterpret_cast<const float2*>(q1 + kb + 8 + 2 * ec);
            uint32_t ah[4], al[4];
            split2(p00.x, p00.y, ah[0], al[0]);
            split2(p10.x, p10.y, ah[1], al[1]);
            split2(p01.x, p01.y, ah[2], al[2]);
            split2(p11.x, p11.y, ah[3], al[3]);
            uint32_t bh[4][4], bl[4][4];
            #pragma unroll
            for (int i = 0; i < 4; i++) {
                uint32_t a = aB1 + (uint32_t)i * 16 * 272 + kk * 32;
                ldsm4(bh[i], a);
                ldsm4(bl[i], a + 17408);
            }
            #pragma unroll
            for (int nt = 0; nt < 8; nt++) {
                const uint32_t* bhp = &bh[nt >> 1][(nt & 1) * 2];
                const uint32_t* blp = &bl[nt >> 1][(nt & 1) * 2];
                mma_bf16(acc1[nt], ah, bhp);
                mma_bf16(acc1[nt], al, bhp);
                mma_bf16(acc1[nt], ah, blp);
            }
        }
        // ---- convert: bias+relu, C-frag -> A-frags of GEMM2 (registers only) ----
        uint32_t fh[4][4], fl[4][4];
        #pragma unroll
        for (int j = 0; j < 4; j++) {
            float2 ba = *reinterpret_cast<const float2*>(b1v + 16 * j + 2 * ec);
            float2 bb = *reinterpret_cast<const float2*>(b1v + 16 * j + 8 + 2 * ec);
            float v;
            float v00 = fmaxf(acc1[2 * j][0] + ba.x, 0.f);
            float v01 = fmaxf(acc1[2 * j][1] + ba.y, 0.f);
            float v10 = fmaxf(acc1[2 * j][2] + ba.x, 0.f);
            float v11 = fmaxf(acc1[2 * j][3] + ba.y, 0.f);
            float w00 = fmaxf(acc1[2 * j + 1][0] + bb.x, 0.f);
            float w01 = fmaxf(acc1[2 * j + 1][1] + bb.y, 0.f);
            float w10 = fmaxf(acc1[2 * j + 1][2] + bb.x, 0.f);
            float w11 = fmaxf(acc1[2 * j + 1][3] + bb.y, 0.f);
            (void)v;
            split2(v00, v01, fh[j][0], fl[j][0]);
            split2(v10, v11, fh[j][1], fl[j][1]);
            split2(w00, w01, fh[j][2], fl[j][2]);
            split2(w10, w11, fh[j][3], fl[j][3]);
        }
        // ---- GEMM2: acc2[m16 x n64] = Mid[m16 x k64] @ B2^T ----
        float acc2[8][4];
        #pragma unroll
        for (int nt = 0; nt < 8; nt++)
            #pragma unroll
            for (int j = 0; j < 4; j++) acc2[nt][j] = 0.f;
        #pragma unroll
        for (int kk = 0; kk < 4; kk++) {
            uint32_t bh[4][4], bl[4][4];
            #pragma unroll
            for (int i = 0; i < 4; i++) {
                uint32_t a = aB2 + (uint32_t)i * 16 * 144 + kk * 32;
                ldsm4(bh[i], a);
                ldsm4(bl[i], a + 9216);
            }
            #pragma unroll
            for (int nt = 0; nt < 8; nt++) {
                const uint32_t* bhp = &bh[nt >> 1][(nt & 1) * 2];
                const uint32_t* blp = &bl[nt >> 1][(nt & 1) * 2];
                mma_bf16(acc2[nt], fh[kk], bhp);
                mma_bf16(acc2[nt], fl[kk], bhp);
                mma_bf16(acc2[nt], fh[kk], blp);
            }
        }
        // ---- epilogue: bias+relu -> scatter/store ----
        #pragma unroll
        for (int nt = 0; nt < 8; nt++) {
            int n = 8 * nt + 2 * ec;
            float2 bb = *reinterpret_cast<const float2*>(b2v + n);
            float v00 = fmaxf(acc2[nt][0] + bb.x, 0.f);
            float v01 = fmaxf(acc2[nt][1] + bb.y, 0.f);
            float v10 = fmaxf(acc2[nt][2] + bb.x, 0.f);
            float v11 = fmaxf(acc2[nt][3] + bb.y, 0.f);
            if (EDGE) {
                float* p0 = g_agg + (size_t)d0 * HID + n;
                float* p1 = g_agg + (size_t)d1 * HID + n;
                asm volatile("red.global.add.v2.f32 [%0], {%1,%2};"
                             :: "l"(p0), "f"(v00), "f"(v01) : "memory");
                asm volatile("red.global.add.v2.f32 [%0], {%1,%2};"
                             :: "l"(p1), "f"(v10), "f"(v11) : "memory");
            } else {
                *reinterpret_cast<float2*>(g_u + (size_t)r0 * HID + n) = make_float2(v00, v01);
                *reinterpret_cast<float2*>(g_u + (size_t)r1 * HID + n) = make_float2(v10, v11);
            }
        }
    }
}

// ---------------- InstanceNorm: 64 blocks = (graph, 16-ch quad) ----------------
__global__ void instnorm_kernel() {
    int g = blockIdx.x >> 2, cq = (blockIdx.x & 3) << 4;
    int t = threadIdx.x;          // 512
    int c = t & 15, r = t >> 4;   // r 0..31
    const float* basep = g_u + (size_t)g * NS * HID + cq + c;
    float* outp = g_h + (size_t)g * NS * HID + cq + c;
    __shared__ float red[32][16];
    float s = 0.f;
    for (int n = r; n < NS; n += 32) s += basep[(size_t)n * HID];
    red[r][c] = s;
    __syncthreads();
    if (r == 0) {
        float tot = 0.f;
        #pragma unroll
        for (int i = 0; i < 32; i++) tot += red[i][c];
        red[0][c] = tot * (1.0f / NS);
    }
    __syncthreads();
    float mean = red[0][c];
    __syncthreads();
    float s2 = 0.f;
    for (int n = r; n < NS; n += 32) {
        float d = basep[(size_t)n * HID] - mean;
        s2 = fmaf(d, d, s2);
    }
    red[r][c] = s2;
    __syncthreads();
    if (r == 0) {
        float tot = 0.f;
        #pragma unroll
        for (int i = 0; i < 32; i++) tot += red[i][c];
        red[0][c] = rsqrtf(tot * (1.0f / NS) + EPSF);
    }
    __syncthreads();
    float inv = red[0][c];
    for (int n = r; n < NS; n += 32)
        outp[(size_t)n * HID] = (basep[(size_t)n * HID] - mean) * inv;
}

// ---------------- decoder ----------------
__global__ void decoder_kernel(const float* __restrict__ W, const float* __restrict__ b,
                               float* __restrict__ out) {
    __shared__ float sW[HID * 3];
    __shared__ float sb[3];
    int t = threadIdx.x;
    if (t < HID * 3) sW[t] = W[t];
    if (t < 3) sb[t] = b[t];
    __syncthreads();
    int n = blockIdx.x * 256 + t;
    float a0 = sb[0], a1 = sb[1], a2 = sb[2];
    const float* hr = g_h + (size_t)n * HID;
    #pragma unroll 8
    for (int k = 0; k < HID; k++) {
        float v = hr[k];
        a0 = fmaf(v, sW[k * 3 + 0], a0);
        a1 = fmaf(v, sW[k * 3 + 1], a1);
        a2 = fmaf(v, sW[k * 3 + 2], a2);
    }
    float inv = rsqrtf(a0 * a0 + a1 * a1 + a2 * a2);
    a0 *= inv; a1 *= inv; a2 *= inv;
    g_X[n * 3 + 0] = a0; g_X[n * 3 + 1] = a1; g_X[n * 3 + 2] = a2;
    out[1 + n * 3 + 0] = a0; out[1 + n * 3 + 1] = a1; out[1 + n * 3 + 2] = a2;
}

// ---------------- MMD kernels ----------------
__global__ void kxx_kernel() {
    int bid = blockIdx.x;
    int g = bid >> 8, tm = (bid >> 4) & 15, tn = bid & 15;
    const float* Xg = g_X + (size_t)g * NS * 3;
    __shared__ float ax[128][4];
    __shared__ float ay[128][4];
    __shared__ float rs[256];
    int t = threadIdx.x;
    for (int i = t; i < 128 * 3; i += 256) {
        int row = i / 3, col = i - row * 3;
        ax[row][col] = Xg[tm * 128 * 3 + i];
        ay[row][col] = Xg[tn * 128 * 3 + i];
    }
    __syncthreads();
    int r0 = (t >> 4) << 3, cb = (t & 15) << 3;
    float yv[8][3];
    #pragma unroll
    for (int j = 0; j < 8; j++) {
        yv[j][0] = ay[cb + j][0]; yv[j][1] = ay[cb + j][1]; yv[j][2] = ay[cb + j][2];
    }
    float s = 0.f;
    #pragma unroll
    for (int i = 0; i < 8; i++) {
        float x0 = ax[r0 + i][0], x1 = ax[r0 + i][1], x2 = ax[r0 + i][2];
        #pragma unroll
        for (int j = 0; j < 8; j++) {
            float d = fmaf(x0, yv[j][0], fmaf(x1, yv[j][1], x2 * yv[j][2]));
            s += fexp(fmaf(2.f, d, -2.f));
        }
    }
    rs[t] = s;
    __syncthreads();
    for (int o = 128; o > 0; o >>= 1) { if (t < o) rs[t] += rs[t + o]; __syncthreads(); }
    if (t == 0) atomicAdd(&g_acc[g], rs[0]);
}

__global__ void kxy_kernel() {
    __shared__ float sy[64][4];
    __shared__ float rs[256];
    int t = threadIdx.x;
    int n = blockIdx.x * 256 + t;
    for (int i = t; i < 64 * 3; i += 256) { int row = i / 3; sy[row][i - row * 3] = g_Y[i]; }
    __syncthreads();
    float x0 = g_X[n * 3], x1 = g_X[n * 3 + 1], x2 = g_X[n * 3 + 2];
    float s = 0.f;
    #pragma unroll 8
    for (int j = 0; j < 64; j++) {
        float d = fmaf(x0, sy[j][0], fmaf(x1, sy[j][1], x2 * sy[j][2]));
        s += fexp(fmaf(2.f, d, -2.f));
    }
    rs[t] = s;
    __syncthreads();
    for (int o = 128; o > 0; o >>= 1) { if (t < o) rs[t] += rs[t + o]; __syncthreads(); }
    if (t == 0) atomicAdd(&g_acc[NBATCH + (n >> 11)], rs[0]);
}

__global__ void finalize_kernel(float* __restrict__ out) {
    __shared__ float rs[64];
    int t = threadIdx.x;
    float x0 = g_Y[t * 3], x1 = g_Y[t * 3 + 1], x2 = g_Y[t * 3 + 2];
    float s = 0.f;
    for (int j = 0; j < 64; j++) {
        float d = fmaf(x0, g_Y[j * 3], fmaf(x1, g_Y[j * 3 + 1], x2 * g_Y[j * 3 + 2]));
        s += fexp(fmaf(2.f, d, -2.f));
    }
    rs[t] = s;
    __syncthreads();
    if (t == 0) {
        float kyy = 0.f;
        for (int j = 0; j < 64; j++) kyy += rs[j];
        kyy *= (1.0f / (64.f * 64.f));
        float loss = 0.f;
        for (int b = 0; b < NBATCH; b++) {
            float kxx = g_acc[b] * (1.0f / ((float)NS * (float)NS));
            float kxy = g_acc[NBATCH + b] * (1.0f / ((float)NS * 64.f));
            loss += kxx - 2.f * kxy + kyy;
        }
        out[0] = loss * (1.0f / NBATCH);
    }
}

// ---------------- launch ----------------
extern "C" void kernel_launch(void* const* d_in, const int* in_sizes, int n_in,
                              void* d_out, int out_size) {
    const float* x    = (const float*)d_in[0];
    const int*   esrc = (const int*)d_in[1];
    const int*   edst = (const int*)d_in[2];
    const float* encW = (const float*)d_in[4];
    const float* encb = (const float*)d_in[5];
    const float* m1W  = (const float*)d_in[6];
    const float* m1b  = (const float*)d_in[7];
    const float* m2W  = (const float*)d_in[8];
    const float* m2b  = (const float*)d_in[9];
    const float* u1W  = (const float*)d_in[10];
    const float* u1b  = (const float*)d_in[11];
    const float* u2W  = (const float*)d_in[12];
    const float* u2b  = (const float*)d_in[13];
    const float* decW = (const float*)d_in[14];
    const float* decb = (const float*)d_in[15];
    float* out = (float*)d_out;

    cudaFuncSetAttribute((const void*)mlp_mma_kernel<true>,
                         cudaFuncAttributeMaxDynamicSharedMemorySize, SMEM_MMA_BYTES);
    cudaFuncSetAttribute((const void*)mlp_mma_kernel<false>,
                         cudaFuncAttributeMaxDynamicSharedMemorySize, SMEM_MMA_BYTES);

    compute_Y_kernel<<<1, 64>>>();
    encoder_kernel<<<NNODES * HID / 256, 256>>>(x, encW, encb);

    for (int l = 0; l < 4; l++) {
        zero_agg_kernel<<<NNODES * HID / 1024, 256>>>();
        mlp_mma_kernel<true><<<296, 256, SMEM_MMA_BYTES>>>(
            m1W + (size_t)l * 128 * 64, m1b + (size_t)l * 64,
            m2W + (size_t)l * 64 * 64,  m2b + (size_t)l * 64, esrc, edst);
        mlp_mma_kernel<false><<<256, 256, SMEM_MMA_BYTES>>>(
            u1W + (size_t)l * 128 * 64, u1b + (size_t)l * 64,
            u2W + (size_t)l * 64 * 64,  u2b + (size_t)l * 64, nullptr, nullptr);
        instnorm_kernel<<<64, 512>>>();
    }

    zero_acc_kernel<<<1, 32>>>();
    decoder_kernel<<<NNODES / 256, 256>>>(decW, decb, out);
    kxy_kernel<<<NNODES / 256, 256>>>();
    kxx_kernel<<<NBATCH * 16 * 16, 256>>>();
    finalize_kernel<<<1, 64>>>(out);
}